// round 11
// baseline (speedup 1.0000x reference)
#include <cuda_runtime.h>
#include <cuda_bf16.h>
#include <math.h>
#include <stdint.h>

// Problem constants
#define B 2
#define S 2048
#define HID 2048
#define NH 16
#define NKV 4
#define HD 128
#define CHUNK 256
#define NCH 8

// Scratch (static device allocations; no cudaMalloc allowed)
__device__ float g_Q[(size_t)B * S * NH * HD];
__device__ float g_K[(size_t)B * S * NKV * HD];
__device__ float g_kmean[(size_t)B * NCH * NKV * HD];
__device__ unsigned g_sel[(size_t)B * NH * S];
__device__ float g_rc[(size_t)S * 64];
__device__ float g_rs[(size_t)S * 64];

// bf16 hi/lo split copies
__device__ __nv_bfloat16 g_xh[(size_t)B * S * HID];
__device__ __nv_bfloat16 g_xl[(size_t)B * S * HID];
__device__ __nv_bfloat16 g_wqh[(size_t)HID * NH * HD];
__device__ __nv_bfloat16 g_wql[(size_t)HID * NH * HD];
__device__ __nv_bfloat16 g_wkh[(size_t)HID * NKV * HD];
__device__ __nv_bfloat16 g_wkl[(size_t)HID * NKV * HD];
__device__ __nv_bfloat16 g_wvh[(size_t)HID * NKV * HD];
__device__ __nv_bfloat16 g_wvl[(size_t)HID * NKV * HD];
__device__ __nv_bfloat16 g_woh[(size_t)NH * HD * HID];
__device__ __nv_bfloat16 g_wol[(size_t)NH * HD * HID];
__device__ __nv_bfloat16 g_oh[(size_t)B * S * NH * HD];
__device__ __nv_bfloat16 g_ol[(size_t)B * S * NH * HD];
// post-RoPE bf16 splits for attention
__device__ __nv_bfloat16 g_Qh[(size_t)B * S * NH * HD];
__device__ __nv_bfloat16 g_Ql[(size_t)B * S * NH * HD];
__device__ __nv_bfloat16 g_Kh[(size_t)B * S * NKV * HD];
__device__ __nv_bfloat16 g_Kl[(size_t)B * S * NKV * HD];
__device__ __nv_bfloat16 g_Vh[(size_t)B * S * NKV * HD];
__device__ __nv_bfloat16 g_Vl[(size_t)B * S * NKV * HD];

// ===========================================================================
// helpers
// ===========================================================================
__device__ __forceinline__ uint32_t smem_u32(const void* p) {
    uint32_t a;
    asm("{ .reg .u64 t; cvta.to.shared.u64 t, %1; cvt.u32.u64 %0, t; }"
        : "=r"(a) : "l"(p));
    return a;
}

__device__ __forceinline__ void ldsm4(uint32_t* r, uint32_t addr) {
    asm volatile("ldmatrix.sync.aligned.m8n8.x4.shared.b16 {%0,%1,%2,%3}, [%4];"
                 : "=r"(r[0]), "=r"(r[1]), "=r"(r[2]), "=r"(r[3]) : "r"(addr));
}
__device__ __forceinline__ void ldsm4t(uint32_t* r, uint32_t addr) {
    asm volatile("ldmatrix.sync.aligned.m8n8.x4.trans.shared.b16 {%0,%1,%2,%3}, [%4];"
                 : "=r"(r[0]), "=r"(r[1]), "=r"(r[2]), "=r"(r[3]) : "r"(addr));
}
__device__ __forceinline__ void mma16816(float* c, const uint32_t* a,
                                         uint32_t b0, uint32_t b1) {
    asm volatile(
        "mma.sync.aligned.m16n8k16.row.col.f32.bf16.bf16.f32 "
        "{%0,%1,%2,%3}, {%4,%5,%6,%7}, {%8,%9}, {%0,%1,%2,%3};"
        : "+f"(c[0]), "+f"(c[1]), "+f"(c[2]), "+f"(c[3])
        : "r"(a[0]), "r"(a[1]), "r"(a[2]), "r"(a[3]), "r"(b0), "r"(b1));
}
__device__ __forceinline__ void cpa16(uint32_t s, const void* g) {
    asm volatile("cp.async.cg.shared.global [%0], [%1], 16;" :: "r"(s), "l"(g));
}

__device__ __forceinline__ void split1(float a, __nv_bfloat16& h, __nv_bfloat16& l) {
    h = __float2bfloat16_rn(a);
    l = __float2bfloat16_rn(a - __bfloat162float(h));
}
__device__ __forceinline__ uint32_t packbf(__nv_bfloat16 lo, __nv_bfloat16 hi) {
    return ((uint32_t)__bfloat16_as_ushort(hi) << 16) | __bfloat16_as_ushort(lo);
}

// ---------------------------------------------------------------------------
// split kernel: fp32 -> bf16 hi + lo (inputs/weights only now)
// ---------------------------------------------------------------------------
__global__ void split_kernel(const float* __restrict__ in,
                             __nv_bfloat16* __restrict__ hi,
                             __nv_bfloat16* __restrict__ lo, int n4) {
    int i = blockIdx.x * blockDim.x + threadIdx.x;
    if (i >= n4) return;
    float4 v = ((const float4*)in)[i];
    __nv_bfloat16 h0, h1, h2, h3, l0, l1, l2, l3;
    split1(v.x, h0, l0);
    split1(v.y, h1, l1);
    split1(v.z, h2, l2);
    split1(v.w, h3, l3);
    ((uint2*)hi)[i] = make_uint2(packbf(h0, h1), packbf(h2, h3));
    ((uint2*)lo)[i] = make_uint2(packbf(l0, l1), packbf(l2, l3));
}

// ===========================================================================
// bf16x3 GEMM mainloop, cp.async 3-stage pipeline, single barrier per iter.
// Accumulators returned in registers for kernel-specific epilogues.
// ===========================================================================
#define GBK 32
#define PAH 0
#define PAL 10240
#define PBH 20480
#define PBL 29184
#define PSTAGE 37888
#define GEMM_SMEM (3 * PSTAGE)

__device__ __forceinline__ void gemm_issue(
    uint32_t st, const __nv_bfloat16* Ah, const __nv_bfloat16* Al,
    const __nv_bfloat16* Bh, const __nv_bfloat16* Bl,
    int bm, int bn, int k0, int N, int K, int tid) {
#pragma unroll
    for (int i = 0; i < 2; i++) {
        int c = tid + i * 256;
        int row = c >> 2, q = c & 3;
        size_t g = (size_t)(bm + row) * K + k0 + q * 8;
        cpa16(st + PAH + row * 80 + q * 16, Ah + g);
        cpa16(st + PAL + row * 80 + q * 16, Al + g);
    }
#pragma unroll
    for (int i = 0; i < 2; i++) {
        int c = tid + i * 256;
        int row = c >> 4, q = c & 15;
        size_t g = (size_t)(k0 + row) * N + bn + q * 8;
        cpa16(st + PBH + row * 272 + q * 16, Bh + g);
        cpa16(st + PBL + row * 272 + q * 16, Bl + g);
    }
    asm volatile("cp.async.commit_group;");
}

__device__ __forceinline__ void gemm_mainloop(
    const __nv_bfloat16* __restrict__ Ah, const __nv_bfloat16* __restrict__ Al,
    const __nv_bfloat16* __restrict__ Bh, const __nv_bfloat16* __restrict__ Bl,
    int N, int K, int bm, int bn, char* smem, float (&acc)[2][8][4]) {
    int tid = threadIdx.x;
    int lane = tid & 31, wid = tid >> 5;
    int wm = wid & 3, wn = wid >> 2;

#pragma unroll
    for (int i = 0; i < 2; i++)
#pragma unroll
        for (int j = 0; j < 8; j++)
#pragma unroll
            for (int k = 0; k < 4; k++) acc[i][j][k] = 0.f;

    uint32_t sb = smem_u32(smem);
    int l15 = lane & 15, l16 = lane >> 4;
    uint32_t a_off = (uint32_t)(wm * 32 + l15) * 80 + l16 * 16;
    uint32_t b_off = (uint32_t)(((lane >> 3) & 1) * 8 + (lane & 7)) * 272
                   + wn * 128 + l16 * 16;

    int niter = K / GBK;
    gemm_issue(sb, Ah, Al, Bh, Bl, bm, bn, 0, N, K, tid);
    gemm_issue(sb + PSTAGE, Ah, Al, Bh, Bl, bm, bn, GBK, N, K, tid);

    int stg = 0;
    for (int it = 0; it < niter; it++) {
        if (it + 1 < niter)
            asm volatile("cp.async.wait_group 1;");
        else
            asm volatile("cp.async.wait_group 0;");
        __syncthreads();
        if (it + 2 < niter) {
            int pst = stg + 2;
            if (pst >= 3) pst -= 3;
            gemm_issue(sb + pst * PSTAGE, Ah, Al, Bh, Bl,
                       bm, bn, (it + 2) * GBK, N, K, tid);
        }

        uint32_t st = sb + stg * PSTAGE;
        uint32_t ash = st + PAH, asl = st + PAL;
        uint32_t bsh = st + PBH, bsl = st + PBL;
#pragma unroll
        for (int ka = 0; ka < 2; ka++) {
            uint32_t ahf[2][4], alf[2][4];
            ldsm4(ahf[0], ash + a_off + ka * 32);
            ldsm4(ahf[1], ash + a_off + ka * 32 + 16 * 80);
            ldsm4(alf[0], asl + a_off + ka * 32);
            ldsm4(alf[1], asl + a_off + ka * 32 + 16 * 80);
#pragma unroll
            for (int nh2 = 0; nh2 < 2; nh2++) {
                uint32_t bhf[2][4], blf[2][4];
                uint32_t bo = b_off + ka * 16 * 272 + nh2 * 64;
                ldsm4t(bhf[0], bsh + bo);
                ldsm4t(bhf[1], bsh + bo + 32);
                ldsm4t(blf[0], bsl + bo);
                ldsm4t(blf[1], bsl + bo + 32);
#pragma unroll
                for (int j = 0; j < 2; j++)
#pragma unroll
                    for (int ma = 0; ma < 2; ma++)
#pragma unroll
                        for (int sub = 0; sub < 2; sub++)
                            mma16816(acc[ma][(nh2 * 2 + j) * 2 + sub], ahf[ma],
                                     bhf[j][sub * 2], bhf[j][sub * 2 + 1]);
#pragma unroll
                for (int j = 0; j < 2; j++)
#pragma unroll
                    for (int ma = 0; ma < 2; ma++)
#pragma unroll
                        for (int sub = 0; sub < 2; sub++)
                            mma16816(acc[ma][(nh2 * 2 + j) * 2 + sub], ahf[ma],
                                     blf[j][sub * 2], blf[j][sub * 2 + 1]);
#pragma unroll
                for (int j = 0; j < 2; j++)
#pragma unroll
                    for (int ma = 0; ma < 2; ma++)
#pragma unroll
                        for (int sub = 0; sub < 2; sub++)
                            mma16816(acc[ma][(nh2 * 2 + j) * 2 + sub], alf[ma],
                                     bhf[j][sub * 2], bhf[j][sub * 2 + 1]);
            }
        }
        if (++stg == 3) stg = 0;
    }
}

// ---------------------------------------------------------------------------
// QKV projection with fused epilogue:
//   Q (bx<16):  rope via smem pairing -> fp32 g_Q + bf16 g_Qh/g_Ql
//   K (16..19): rope via smem pairing -> fp32 g_K + bf16 g_Kh/g_Kl
//   V (20..23): direct in-register split -> bf16 g_Vh/g_Vl only
// ---------------------------------------------------------------------------
__global__ __launch_bounds__(256, 2)
void gemm_qkv_kernel() {
    extern __shared__ char smem[];
    int bx = blockIdx.x;
    int bm = blockIdx.y * 128;
    int tid = threadIdx.x;
    int lane = tid & 31, wid = tid >> 5;
    int wm = wid & 3, wn = wid >> 2;

    const __nv_bfloat16 *Bh, *Bl;
    int N, bn;
    if (bx < 16) {
        Bh = g_wqh; Bl = g_wql; N = NH * HD; bn = bx * 128;
    } else if (bx < 20) {
        Bh = g_wkh; Bl = g_wkl; N = NKV * HD; bn = (bx - 16) * 128;
    } else {
        Bh = g_wvh; Bl = g_wvl; N = NKV * HD; bn = (bx - 20) * 128;
    }

    float acc[2][8][4];
    gemm_mainloop(g_xh, g_xl, Bh, Bl, N, HID, bm, bn, smem, acc);

    if (bx >= 20) {
        // V: direct bf16 split (no rope); no smem use, no extra sync needed.
#pragma unroll
        for (int ma = 0; ma < 2; ma++) {
            int row0 = bm + wm * 32 + ma * 16 + (lane >> 2);
#pragma unroll
            for (int na = 0; na < 8; na++) {
                int col = bn + wn * 64 + na * 8 + (lane & 3) * 2;
                __nv_bfloat16 h0, l0, h1, l1;
                split1(acc[ma][na][0], h0, l0);
                split1(acc[ma][na][1], h1, l1);
                *(uint32_t*)(g_Vh + (size_t)row0 * 512 + col) = packbf(h0, h1);
                *(uint32_t*)(g_Vl + (size_t)row0 * 512 + col) = packbf(l0, l1);
                split1(acc[ma][na][2], h0, l0);
                split1(acc[ma][na][3], h1, l1);
                *(uint32_t*)(g_Vh + (size_t)(row0 + 8) * 512 + col) = packbf(h0, h1);
                *(uint32_t*)(g_Vl + (size_t)(row0 + 8) * 512 + col) = packbf(l0, l1);
            }
        }
        return;
    }

    // Q/K: stage fp32 tile to smem for rope pairing (all warps finished the
    // mainloop smem reads; barrier before reuse).
    __syncthreads();
    float* sf = (float*)smem;   // [128][132]
#pragma unroll
    for (int ma = 0; ma < 2; ma++) {
        int rl = wm * 32 + ma * 16 + (lane >> 2);
#pragma unroll
        for (int na = 0; na < 8; na++) {
            int cl = wn * 64 + na * 8 + (lane & 3) * 2;
            *(float2*)&sf[rl * 132 + cl] = make_float2(acc[ma][na][0], acc[ma][na][1]);
            *(float2*)&sf[(rl + 8) * 132 + cl] = make_float2(acc[ma][na][2], acc[ma][na][3]);
        }
    }
    __syncthreads();

    bool isQ = (bx < 16);
    int hd_total = isQ ? NH * HD : NKV * HD;
    float* fout = isQ ? g_Q : g_K;
    __nv_bfloat16* ho = isQ ? g_Qh : g_Kh;
    __nv_bfloat16* lo = isQ ? g_Ql : g_Kl;

    int j = tid & 63, rg = tid >> 6;
#pragma unroll 4
    for (int rr = 0; rr < 32; rr++) {
        int r = rg * 32 + rr;
        int grow = bm + r;
        int s = grow & (S - 1);
        float c = g_rc[s * 64 + j];
        float sn = g_rs[s * 64 + j];
        float x1 = sf[r * 132 + j], x2 = sf[r * 132 + j + 64];
        float y1 = x1 * c - x2 * sn;
        float y2 = x2 * c + x1 * sn;
        size_t base = (size_t)grow * hd_total + bn;
        fout[base + j] = y1;
        fout[base + j + 64] = y2;
        __nv_bfloat16 h1, l1, h2, l2;
        split1(y1, h1, l1);
        split1(y2, h2, l2);
        ho[base + j] = h1;
        lo[base + j] = l1;
        ho[base + j + 64] = h2;
        lo[base + j + 64] = l2;
    }
}

// Output projection: plain fp32 epilogue.
__global__ __launch_bounds__(256, 2)
void gemm_out_kernel(float* __restrict__ C) {
    extern __shared__ char smem[];
    int tid = threadIdx.x;
    int lane = tid & 31, wid = tid >> 5;
    int wm = wid & 3, wn = wid >> 2;
    int bm = blockIdx.y * 128, bn = blockIdx.x * 128;

    float acc[2][8][4];
    gemm_mainloop(g_oh, g_ol, g_woh, g_wol, HID, NH * HD, bm, bn, smem, acc);

#pragma unroll
    for (int ma = 0; ma < 2; ma++) {
        int row = bm + wm * 32 + ma * 16 + (lane >> 2);
#pragma unroll
        for (int na = 0; na < 8; na++) {
            int col = bn + wn * 64 + na * 8 + (lane & 3) * 2;
            *(float2*)(C + (size_t)row * HID + col) =
                make_float2(acc[ma][na][0], acc[ma][na][1]);
            *(float2*)(C + (size_t)(row + 8) * HID + col) =
                make_float2(acc[ma][na][2], acc[ma][na][3]);
        }
    }
}

// ---------------------------------------------------------------------------
// RoPE table
// ---------------------------------------------------------------------------
__global__ void rope_table_kernel() {
    int i = blockIdx.x * blockDim.x + threadIdx.x;
    if (i >= S * 64) return;
    int j = i & 63;
    int s = i >> 6;
    double ifd = exp(-((double)(2 * j) / 128.0) * log(10000.0));
    float invf = (float)ifd;
    float ang = (float)s * invf;
    double cd, sd;
    sincos((double)ang, &sd, &cd);
    g_rc[i] = (float)cd;
    g_rs[i] = (float)sd;
}

// ---------------------------------------------------------------------------
// Per-chunk K mean + selection
// ---------------------------------------------------------------------------
__global__ void kmean_kernel() {
    int id = blockIdx.x;
    int kvh = id & 3;
    int n = (id >> 2) & 7;
    int b = id >> 5;
    int d = threadIdx.x;
    const float* base = g_K + (((size_t)b * S + n * CHUNK) * NKV + kvh) * HD + d;
    float s = 0.f;
#pragma unroll 8
    for (int i = 0; i < CHUNK; i++) s += base[(size_t)i * NKV * HD];
    g_kmean[((b * NCH + n) * NKV + kvh) * HD + d] = s * (1.0f / CHUNK);
}

__global__ void select_kernel() {
    int w = blockIdx.x * (blockDim.x >> 5) + (threadIdx.x >> 5);
    int lane = threadIdx.x & 31;
    int s = w & (S - 1);
    int h = (w >> 11) & (NH - 1);
    int b = w >> 15;
    int kvh = h >> 2;
    int qc = s >> 8;

    const float* q = g_Q + (((size_t)b * S + s) * NH + h) * HD;
    float4 qv = *(const float4*)(q + lane * 4);
    float g[8];
    for (int n = 0; n < qc; n++) {
        const float* km = g_kmean + ((b * NCH + n) * NKV + kvh) * HD;
        float4 kv = *(const float4*)(km + lane * 4);
        float p = qv.x * kv.x + qv.y * kv.y + qv.z * kv.z + qv.w * kv.w;
#pragma unroll
        for (int o = 16; o; o >>= 1) p += __shfl_xor_sync(0xffffffffu, p, o);
        g[n] = p;
    }
    if (lane == 0) {
        unsigned sel = 1u << qc;
        for (int it = 0; it < 3; it++) {
            float best = 0.f;
            int bi = -1;
            for (int n = 0; n < qc; n++)
                if (!((sel >> n) & 1) && (bi < 0 || g[n] > best)) { best = g[n]; bi = n; }
            if (bi >= 0) sel |= 1u << bi;
        }
        g_sel[w] = sel;
    }
}

// ===========================================================================
// Tensor-core sparse flash attention, 3-stage cp.async K/V pipeline +
// per-warp chunk skip + identity-rescale skip.
// ===========================================================================
#define AQ 128
#define AK 32
#define ASTR 136

#define KVSTAGE_B (4 * AK * ASTR * 2)
#define OFF_KH 0
#define OFF_KL (AK * ASTR * 2)
#define OFF_VH (2 * AK * ASTR * 2)
#define OFF_VL (3 * AK * ASTR * 2)
#define AT_Q_ELEMS (2 * AQ * ASTR)
#define AT_KV0_B (AT_Q_ELEMS * 2)
#define AT_BF16_B (AT_KV0_B + 3 * KVSTAGE_B)
#define AT_SMEM_BYTES (AT_BF16_B + AQ * 4 + 16 + 160)

__device__ __forceinline__ void attn_issue_kv(uint32_t st, int b, int kvh,
                                              int kt, int tid) {
    int row = tid >> 3;
    size_t gk = (((size_t)b * S + kt * AK + row) * NKV + kvh) * HD;
#pragma unroll
    for (int i = 0; i < 2; i++) {
        int g = (tid & 7) * 2 + i;
        uint32_t off = row * 272 + g * 16;
        cpa16(st + OFF_KH + off, g_Kh + gk + g * 8);
        cpa16(st + OFF_KL + off, g_Kl + gk + g * 8);
        cpa16(st + OFF_VH + off, g_Vh + gk + g * 8);
        cpa16(st + OFF_VL + off, g_Vl + gk + g * 8);
    }
    asm volatile("cp.async.commit_group;");
}

__global__ __launch_bounds__(256)
void attn_mma_kernel() {
    extern __shared__ __align__(16) char smc[];
    __nv_bfloat16* sQh = (__nv_bfloat16*)smc;
    __nv_bfloat16* sQl = sQh + AQ * ASTR;
    unsigned* selq = (unsigned*)(smc + AT_BF16_B);
    unsigned* selu_p = selq + AQ;
    int* cnt_p = (int*)(selu_p + 1);
    short* list = (short*)(cnt_p + 1);

    int qt = gridDim.x - 1 - blockIdx.x;
    int h = blockIdx.y, b = blockIdx.z;
    int kvh = h >> 2;
    int tid = threadIdx.x, lane = tid & 31, w = tid >> 5;
    int s0 = qt * AQ;
    int qc = s0 >> 8;

    {
        int r = tid >> 1, half = tid & 1;
        size_t gq = (((size_t)b * S + s0 + r) * NH + h) * HD + half * 64;
#pragma unroll
        for (int i = 0; i < 8; i++) {
            *(uint4*)&sQh[r * ASTR + half * 64 + i * 8] = *(const uint4*)(g_Qh + gq + i * 8);
            *(uint4*)&sQl[r * ASTR + half * 64 + i * 8] = *(const uint4*)(g_Ql + gq + i * 8);
        }
    }
    if (tid == 0) *selu_p = 0;
    __syncthreads();
    if (tid < AQ) {
        unsigned sv = g_sel[((size_t)(b * NH + h) << 11) + s0 + tid];
        selq[tid] = sv;
        atomicOr(selu_p, sv);
    }
    __syncthreads();
    if (tid == 0) {
        unsigned selu = *selu_p;
        int nkt = (s0 >> 5) + 4;
        int c = 0;
        for (int kt = 0; kt < nkt; kt++) {
            int n = kt >> 3;
            if (n < qc && !((selu >> n) & 1)) continue;
            list[c++] = (short)kt;
        }
        *cnt_p = c;
    }
    __syncthreads();
    int cnt = *cnt_p;

    unsigned selw = 0;
#pragma unroll
    for (int i = 0; i < 16; i++) selw |= selq[w * 16 + i];

    uint32_t kv0 = smem_u32(smc + AT_KV0_B);
    attn_issue_kv(kv0, b, kvh, list[0], tid);
    if (cnt > 1) attn_issue_kv(kv0 + KVSTAGE_B, b, kvh, list[1], tid);

    float acc[16][4];
#pragma unroll
    for (int j = 0; j < 16; j++)
#pragma unroll
        for (int k = 0; k < 4; k++) acc[j][k] = 0.f;
    float m0 = -1e30f, m1 = -1e30f, l0 = 0.f, l1 = 0.f;

    const float scale = 0.08838834764831845f;

    uint32_t qh_b = smem_u32(sQh), ql_b = smem_u32(sQl);
    uint32_t a_off = (uint32_t)(w * 16 + (lane & 15)) * 272 + (lane >> 4) * 16;
    uint32_t k_off = (uint32_t)((lane & 7) + (lane >> 4) * 8) * 272 + ((lane >> 3) & 1) * 16;
    uint32_t v_off = (uint32_t)(((lane >> 3) & 1) * 8 + (lane & 7)) * 272 + (lane >> 4) * 16;

    int r0 = w * 16 + (lane >> 2);
    int r1 = r0 + 8;

    int stg = 0;
    for (int i = 0; i < cnt; i++) {
        if (i + 1 < cnt)
            asm volatile("cp.async.wait_group 1;");
        else
            asm volatile("cp.async.wait_group 0;");
        __syncthreads();
        if (i + 2 < cnt) {
            int pst = stg + 2;
            if (pst >= 3) pst -= 3;
            attn_issue_kv(kv0 + pst * KVSTAGE_B, b, kvh, list[i + 2], tid);
        }

        int kt = list[i];
        int n = kt >> 3;
        bool past = (n < qc);
        uint32_t st = kv0 + stg * KVSTAGE_B;
        if (++stg == 3) stg = 0;

        if (past && !((selw >> n) & 1)) continue;

        uint32_t kh_b = st + OFF_KH, kl_b = st + OFF_KL;
        uint32_t vh_b = st + OFF_VH, vl_b = st + OFF_VL;

        float s[4][4];
#pragma unroll
        for (int nt = 0; nt < 4; nt++)
#pragma unroll
            for (int k = 0; k < 4; k++) s[nt][k] = 0.f;
#pragma unroll
        for (int ka = 0; ka < 8; ka++) {
            uint32_t aqh[4], aql[4], bh0[4], bh1[4], bl0[4], bl1[4];
            ldsm4(aqh, qh_b + a_off + ka * 32);
            ldsm4(aql, ql_b + a_off + ka * 32);
            ldsm4(bh0, kh_b + k_off + ka * 32);
            ldsm4(bh1, kh_b + k_off + 16 * 272 + ka * 32);
            ldsm4(bl0, kl_b + k_off + ka * 32);
            ldsm4(bl1, kl_b + k_off + 16 * 272 + ka * 32);
            mma16816(s[0], aqh, bh0[0], bh0[1]);
            mma16816(s[1], aqh, bh0[2], bh0[3]);
            mma16816(s[2], aqh, bh1[0], bh1[1]);
            mma16816(s[3], aqh, bh1[2], bh1[3]);
            mma16816(s[0], aqh, bl0[0], bl0[1]);
            mma16816(s[1], aqh, bl0[2], bl0[3]);
            mma16816(s[2], aqh, bl1[0], bl1[1]);
            mma16816(s[3], aqh, bl1[2], bl1[3]);
            mma16816(s[0], aql, bh0[0], bh0[1]);
            mma16816(s[1], aql, bh0[2], bh0[3]);
            mma16816(s[2], aql, bh1[0], bh1[1]);
            mma16816(s[3], aql, bh1[2], bh1[3]);
        }

        if (past) {
            bool ok0 = (selq[r0] >> n) & 1, ok1 = (selq[r1] >> n) & 1;
#pragma unroll
            for (int nt = 0; nt < 4; nt++) {
                s[nt][0] = ok0 ? s[nt][0] * scale : -3.0e38f;
                s[nt][1] = ok0 ? s[nt][1] * scale : -3.0e38f;
                s[nt][2] = ok1 ? s[nt][2] * scale : -3.0e38f;
                s[nt][3] = ok1 ? s[nt][3] * scale : -3.0e38f;
            }
        } else {
            int q0 = s0 + r0, q1 = s0 + r1;
#pragma unroll
            for (int nt = 0; nt < 4; nt++) {
                int t = kt * 32 + nt * 8 + (lane & 3) * 2;
                s[nt][0] = (t     <= q0) ? s[nt][0] * scale : -3.0e38f;
                s[nt][1] = (t + 1 <= q0) ? s[nt][1] * scale : -3.0e38f;
                s[nt][2] = (t     <= q1) ? s[nt][2] * scale : -3.0e38f;
                s[nt][3] = (t + 1 <= q1) ? s[nt][3] * scale : -3.0e38f;
            }
        }

        float mx0 = -3.0e38f, mx1 = -3.0e38f;
#pragma unroll
        for (int nt = 0; nt < 4; nt++) {
            mx0 = fmaxf(mx0, fmaxf(s[nt][0], s[nt][1]));
            mx1 = fmaxf(mx1, fmaxf(s[nt][2], s[nt][3]));
        }
        mx0 = fmaxf(mx0, __shfl_xor_sync(0xffffffffu, mx0, 1));
        mx0 = fmaxf(mx0, __shfl_xor_sync(0xffffffffu, mx0, 2));
        mx1 = fmaxf(mx1, __shfl_xor_sync(0xffffffffu, mx1, 1));
        mx1 = fmaxf(mx1, __shfl_xor_sync(0xffffffffu, mx1, 2));
        float mn0 = fmaxf(m0, mx0), mn1 = fmaxf(m1, mx1);
        float f0 = __expf(m0 - mn0), f1 = __expf(m1 - mn1);

        float sum0 = 0.f, sum1 = 0.f;
        uint32_t ph[4][2], pl[4][2];
#pragma unroll
        for (int nt = 0; nt < 4; nt++) {
            float p0 = __expf(s[nt][0] - mn0);
            float p1 = __expf(s[nt][1] - mn0);
            float p2 = __expf(s[nt][2] - mn1);
            float p3 = __expf(s[nt][3] - mn1);
            sum0 += p0 + p1;
            sum1 += p2 + p3;
            __nv_bfloat16 h0, h1, h2, h3, q0b, q1b, q2b, q3b;
            split1(p0, h0, q0b);
            split1(p1, h1, q1b);
            split1(p2, h2, q2b);
            split1(p3, h3, q3b);
            ph[nt][0] = packbf(h0, h1);
            ph[nt][1] = packbf(h2, h3);
            pl[nt][0] = packbf(q0b, q1b);
            pl[nt][1] = packbf(q2b, q3b);
        }
        sum0 += __shfl_xor_sync(0xffffffffu, sum0, 1);
        sum0 += __shfl_xor_sync(0xffffffffu, sum0, 2);
        sum1 += __shfl_xor_sync(0xffffffffu, sum1, 1);
        sum1 += __shfl_xor_sync(0xffffffffu, sum1, 2);
        l0 = l0 * f0 + sum0;
        l1 = l1 * f1 + sum1;
        m0 = mn0;
        m1 = mn1;
        // Identity-rescale skip: if no lane's max changed, f==1.0 exactly and
        // the multiplies are identities -> skipping is bit-identical.
        if (!__all_sync(0xffffffffu, (mn0 == m0) && (mn1 == m1) && f0 == 1.f && f1 == 1.f)) {
#pragma unroll
            for (int j = 0; j < 16; j++) {
                acc[j][0] *= f0;
                acc[j][1] *= f0;
                acc[j][2] *= f1;
                acc[j][3] *= f1;
            }
        }

#pragma unroll
        for (int kg = 0; kg < 2; kg++) {
            uint32_t aPh[4] = {ph[kg * 2][0], ph[kg * 2][1], ph[kg * 2 + 1][0], ph[kg * 2 + 1][1]};
            uint32_t aPl[4] = {pl[kg * 2][0], pl[kg * 2][1], pl[kg * 2 + 1][0], pl[kg * 2 + 1][1]};
#pragma unroll
            for (int dn = 0; dn < 8; dn++) {
                uint32_t bvh[4], bvl[4];
                ldsm4t(bvh, vh_b + v_off + kg * 16 * 272 + dn * 32);
                ldsm4t(bvl, vl_b + v_off + kg * 16 * 272 + dn * 32);
                mma16816(acc[dn * 2],     aPh, bvh[0], bvh[1]);
                mma16816(acc[dn * 2 + 1], aPh, bvh[2], bvh[3]);
                mma16816(acc[dn * 2],     aPh, bvl[0], bvl[1]);
                mma16816(acc[dn * 2 + 1], aPh, bvl[2], bvl[3]);
                mma16816(acc[dn * 2],     aPl, bvh[0], bvh[1]);
                mma16816(acc[dn * 2 + 1], aPl, bvh[2], bvh[3]);
            }
        }
    }

    float inv0 = 1.0f / l0, inv1 = 1.0f / l1;
    size_t ob0 = (((size_t)b * S + s0 + r0) * NH + h) * HD;
    size_t ob1 = (((size_t)b * S + s0 + r1) * NH + h) * HD;
#pragma unroll
    for (int j = 0; j < 16; j++) {
        int d = j * 8 + (lane & 3) * 2;
        float o0 = acc[j][0] * inv0, o1 = acc[j][1] * inv0;
        float o2 = acc[j][2] * inv1, o3 = acc[j][3] * inv1;
        __nv_bfloat16 h0, h1, h2, h3, q0b, q1b, q2b, q3b;
        split1(o0, h0, q0b);
        split1(o1, h1, q1b);
        split1(o2, h2, q2b);
        split1(o3, h3, q3b);
        *(uint32_t*)(g_oh + ob0 + d) = packbf(h0, h1);
        *(uint32_t*)(g_ol + ob0 + d) = packbf(q0b, q1b);
        *(uint32_t*)(g_oh + ob1 + d) = packbf(h2, h3);
        *(uint32_t*)(g_ol + ob1 + d) = packbf(q2b, q3b);
    }
}

// ---------------------------------------------------------------------------
extern "C" void kernel_launch(void* const* d_in, const int* in_sizes, int n_in,
                              void* d_out, int out_size) {
    const float* x  = (const float*)d_in[0];
    const float* wq = (const float*)d_in[1];
    const float* wk = (const float*)d_in[2];
    const float* wv = (const float*)d_in[3];
    const float* wo = (const float*)d_in[4];
    float* out = (float*)d_out;

    __nv_bfloat16 *xh, *xl, *wqh, *wql, *wkh, *wkl, *wvh, *wvl, *woh, *wol;
    cudaGetSymbolAddress((void**)&xh, g_xh);
    cudaGetSymbolAddress((void**)&xl, g_xl);
    cudaGetSymbolAddress((void**)&wqh, g_wqh);
    cudaGetSymbolAddress((void**)&wql, g_wql);
    cudaGetSymbolAddress((void**)&wkh, g_wkh);
    cudaGetSymbolAddress((void**)&wkl, g_wkl);
    cudaGetSymbolAddress((void**)&wvh, g_wvh);
    cudaGetSymbolAddress((void**)&wvl, g_wvl);
    cudaGetSymbolAddress((void**)&woh, g_woh);
    cudaGetSymbolAddress((void**)&wol, g_wol);

    const int M = B * S;  // 4096
    cudaFuncSetAttribute(attn_mma_kernel,
                         cudaFuncAttributeMaxDynamicSharedMemorySize, AT_SMEM_BYTES);
    cudaFuncSetAttribute(gemm_qkv_kernel,
                         cudaFuncAttributeMaxDynamicSharedMemorySize, GEMM_SMEM);
    cudaFuncSetAttribute(gemm_out_kernel,
                         cudaFuncAttributeMaxDynamicSharedMemorySize, GEMM_SMEM);

    rope_table_kernel<<<(S * 64 + 255) / 256, 256>>>();

    // pre-split inputs/weights
    {
        int n4;
        n4 = (M * HID) / 4;
        split_kernel<<<(n4 + 255) / 256, 256>>>(x, xh, xl, n4);
        n4 = (HID * NH * HD) / 4;
        split_kernel<<<(n4 + 255) / 256, 256>>>(wq, wqh, wql, n4);
        n4 = (HID * NKV * HD) / 4;
        split_kernel<<<(n4 + 255) / 256, 256>>>(wk, wkh, wkl, n4);
        split_kernel<<<(n4 + 255) / 256, 256>>>(wv, wvh, wvl, n4);
        n4 = (NH * HD * HID) / 4;
        split_kernel<<<(n4 + 255) / 256, 256>>>(wo, woh, wol, n4);
    }

    // fused Q/K/V projections with rope+split epilogue
    gemm_qkv_kernel<<<dim3(24, 32), 256, GEMM_SMEM>>>();

    // chunk means + selection
    kmean_kernel<<<B * NCH * NKV, 128>>>();
    select_kernel<<<(B * NH * S) / 8, 256>>>();

    // tensor-core sparse attention
    attn_mma_kernel<<<dim3(S / AQ, NH, B), 256, AT_SMEM_BYTES>>>();

    // output projection
    gemm_out_kernel<<<dim3(16, 32), 256, GEMM_SMEM>>>(out);
}

// round 13
// speedup vs baseline: 1.0065x; 1.0065x over previous
#include <cuda_runtime.h>
#include <cuda_bf16.h>
#include <math.h>
#include <stdint.h>

// Problem constants
#define B 2
#define S 2048
#define HID 2048
#define NH 16
#define NKV 4
#define HD 128
#define CHUNK 256
#define NCH 8

// Scratch (static device allocations; no cudaMalloc allowed)
__device__ float g_Q[(size_t)B * S * NH * HD];
__device__ float g_K[(size_t)B * S * NKV * HD];
__device__ float g_kmean[(size_t)B * NCH * NKV * HD];
__device__ unsigned g_sel[(size_t)B * NH * S];
__device__ float g_rc[(size_t)S * 64];
__device__ float g_rs[(size_t)S * 64];

// bf16 hi/lo split copies
__device__ __nv_bfloat16 g_xh[(size_t)B * S * HID];
__device__ __nv_bfloat16 g_xl[(size_t)B * S * HID];
__device__ __nv_bfloat16 g_wqh[(size_t)HID * NH * HD];
__device__ __nv_bfloat16 g_wql[(size_t)HID * NH * HD];
__device__ __nv_bfloat16 g_wkh[(size_t)HID * NKV * HD];
__device__ __nv_bfloat16 g_wkl[(size_t)HID * NKV * HD];
__device__ __nv_bfloat16 g_wvh[(size_t)HID * NKV * HD];
__device__ __nv_bfloat16 g_wvl[(size_t)HID * NKV * HD];
__device__ __nv_bfloat16 g_woh[(size_t)NH * HD * HID];
__device__ __nv_bfloat16 g_wol[(size_t)NH * HD * HID];
__device__ __nv_bfloat16 g_oh[(size_t)B * S * NH * HD];
__device__ __nv_bfloat16 g_ol[(size_t)B * S * NH * HD];
// post-RoPE bf16 splits for attention
__device__ __nv_bfloat16 g_Qh[(size_t)B * S * NH * HD];
__device__ __nv_bfloat16 g_Ql[(size_t)B * S * NH * HD];
__device__ __nv_bfloat16 g_Kh[(size_t)B * S * NKV * HD];
__device__ __nv_bfloat16 g_Kl[(size_t)B * S * NKV * HD];
__device__ __nv_bfloat16 g_Vh[(size_t)B * S * NKV * HD];
__device__ __nv_bfloat16 g_Vl[(size_t)B * S * NKV * HD];

// ===========================================================================
// helpers
// ===========================================================================
__device__ __forceinline__ uint32_t smem_u32(const void* p) {
    uint32_t a;
    asm("{ .reg .u64 t; cvta.to.shared.u64 t, %1; cvt.u32.u64 %0, t; }"
        : "=r"(a) : "l"(p));
    return a;
}

__device__ __forceinline__ void ldsm4(uint32_t* r, uint32_t addr) {
    asm volatile("ldmatrix.sync.aligned.m8n8.x4.shared.b16 {%0,%1,%2,%3}, [%4];"
                 : "=r"(r[0]), "=r"(r[1]), "=r"(r[2]), "=r"(r[3]) : "r"(addr));
}
__device__ __forceinline__ void ldsm4t(uint32_t* r, uint32_t addr) {
    asm volatile("ldmatrix.sync.aligned.m8n8.x4.trans.shared.b16 {%0,%1,%2,%3}, [%4];"
                 : "=r"(r[0]), "=r"(r[1]), "=r"(r[2]), "=r"(r[3]) : "r"(addr));
}
__device__ __forceinline__ void mma16816(float* c, const uint32_t* a,
                                         uint32_t b0, uint32_t b1) {
    asm volatile(
        "mma.sync.aligned.m16n8k16.row.col.f32.bf16.bf16.f32 "
        "{%0,%1,%2,%3}, {%4,%5,%6,%7}, {%8,%9}, {%0,%1,%2,%3};"
        : "+f"(c[0]), "+f"(c[1]), "+f"(c[2]), "+f"(c[3])
        : "r"(a[0]), "r"(a[1]), "r"(a[2]), "r"(a[3]), "r"(b0), "r"(b1));
}
__device__ __forceinline__ void cpa16(uint32_t s, const void* g) {
    asm volatile("cp.async.cg.shared.global [%0], [%1], 16;" :: "r"(s), "l"(g));
}

__device__ __forceinline__ void split1(float a, __nv_bfloat16& h, __nv_bfloat16& l) {
    h = __float2bfloat16_rn(a);
    l = __float2bfloat16_rn(a - __bfloat162float(h));
}
__device__ __forceinline__ uint32_t packbf(__nv_bfloat16 lo, __nv_bfloat16 hi) {
    return ((uint32_t)__bfloat16_as_ushort(hi) << 16) | __bfloat16_as_ushort(lo);
}

// ---------------------------------------------------------------------------
// merged split kernel: 5 fp32->bf16 hi/lo segments in one launch
// ---------------------------------------------------------------------------
struct SplitArgs {
    const float* in[5];
    __nv_bfloat16* hi[5];
    __nv_bfloat16* lo[5];
    int start[5];   // cumulative quad offsets; start[0]=0
    int total;      // total quads
};

__global__ void split5_kernel(SplitArgs a) {
    int i = blockIdx.x * blockDim.x + threadIdx.x;
    if (i >= a.total) return;
    int seg = 0;
#pragma unroll
    for (int s = 1; s < 5; s++)
        if (i >= a.start[s]) seg = s;
    int j = i - a.start[seg];
    float4 v = ((const float4*)a.in[seg])[j];
    __nv_bfloat16 h0, h1, h2, h3, l0, l1, l2, l3;
    split1(v.x, h0, l0);
    split1(v.y, h1, l1);
    split1(v.z, h2, l2);
    split1(v.w, h3, l3);
    ((uint2*)a.hi[seg])[j] = make_uint2(packbf(h0, h1), packbf(h2, h3));
    ((uint2*)a.lo[seg])[j] = make_uint2(packbf(l0, l1), packbf(l2, l3));
}

// ===========================================================================
// bf16x3 GEMM mainloop, cp.async 3-stage pipeline, single barrier per iter.
// ===========================================================================
#define GBK 32
#define PAH 0
#define PAL 10240
#define PBH 20480
#define PBL 29184
#define PSTAGE 37888
#define GEMM_SMEM (3 * PSTAGE)

__device__ __forceinline__ void gemm_issue(
    uint32_t st, const __nv_bfloat16* Ah, const __nv_bfloat16* Al,
    const __nv_bfloat16* Bh, const __nv_bfloat16* Bl,
    int bm, int bn, int k0, int N, int K, int tid) {
#pragma unroll
    for (int i = 0; i < 2; i++) {
        int c = tid + i * 256;
        int row = c >> 2, q = c & 3;
        size_t g = (size_t)(bm + row) * K + k0 + q * 8;
        cpa16(st + PAH + row * 80 + q * 16, Ah + g);
        cpa16(st + PAL + row * 80 + q * 16, Al + g);
    }
#pragma unroll
    for (int i = 0; i < 2; i++) {
        int c = tid + i * 256;
        int row = c >> 4, q = c & 15;
        size_t g = (size_t)(k0 + row) * N + bn + q * 8;
        cpa16(st + PBH + row * 272 + q * 16, Bh + g);
        cpa16(st + PBL + row * 272 + q * 16, Bl + g);
    }
    asm volatile("cp.async.commit_group;");
}

__device__ __forceinline__ void gemm_mainloop(
    const __nv_bfloat16* __restrict__ Ah, const __nv_bfloat16* __restrict__ Al,
    const __nv_bfloat16* __restrict__ Bh, const __nv_bfloat16* __restrict__ Bl,
    int N, int K, int bm, int bn, char* smem, float (&acc)[2][8][4]) {
    int tid = threadIdx.x;
    int lane = tid & 31, wid = tid >> 5;
    int wm = wid & 3, wn = wid >> 2;

#pragma unroll
    for (int i = 0; i < 2; i++)
#pragma unroll
        for (int j = 0; j < 8; j++)
#pragma unroll
            for (int k = 0; k < 4; k++) acc[i][j][k] = 0.f;

    uint32_t sb = smem_u32(smem);
    int l15 = lane & 15, l16 = lane >> 4;
    uint32_t a_off = (uint32_t)(wm * 32 + l15) * 80 + l16 * 16;
    uint32_t b_off = (uint32_t)(((lane >> 3) & 1) * 8 + (lane & 7)) * 272
                   + wn * 128 + l16 * 16;

    int niter = K / GBK;
    gemm_issue(sb, Ah, Al, Bh, Bl, bm, bn, 0, N, K, tid);
    gemm_issue(sb + PSTAGE, Ah, Al, Bh, Bl, bm, bn, GBK, N, K, tid);

    int stg = 0;
    for (int it = 0; it < niter; it++) {
        if (it + 1 < niter)
            asm volatile("cp.async.wait_group 1;");
        else
            asm volatile("cp.async.wait_group 0;");
        __syncthreads();
        if (it + 2 < niter) {
            int pst = stg + 2;
            if (pst >= 3) pst -= 3;
            gemm_issue(sb + pst * PSTAGE, Ah, Al, Bh, Bl,
                       bm, bn, (it + 2) * GBK, N, K, tid);
        }

        uint32_t st = sb + stg * PSTAGE;
        uint32_t ash = st + PAH, asl = st + PAL;
        uint32_t bsh = st + PBH, bsl = st + PBL;
#pragma unroll
        for (int ka = 0; ka < 2; ka++) {
            uint32_t ahf[2][4], alf[2][4];
            ldsm4(ahf[0], ash + a_off + ka * 32);
            ldsm4(ahf[1], ash + a_off + ka * 32 + 16 * 80);
            ldsm4(alf[0], asl + a_off + ka * 32);
            ldsm4(alf[1], asl + a_off + ka * 32 + 16 * 80);
#pragma unroll
            for (int nh2 = 0; nh2 < 2; nh2++) {
                uint32_t bhf[2][4], blf[2][4];
                uint32_t bo = b_off + ka * 16 * 272 + nh2 * 64;
                ldsm4t(bhf[0], bsh + bo);
                ldsm4t(bhf[1], bsh + bo + 32);
                ldsm4t(blf[0], bsl + bo);
                ldsm4t(blf[1], bsl + bo + 32);
#pragma unroll
                for (int j = 0; j < 2; j++)
#pragma unroll
                    for (int ma = 0; ma < 2; ma++)
#pragma unroll
                        for (int sub = 0; sub < 2; sub++)
                            mma16816(acc[ma][(nh2 * 2 + j) * 2 + sub], ahf[ma],
                                     bhf[j][sub * 2], bhf[j][sub * 2 + 1]);
#pragma unroll
                for (int j = 0; j < 2; j++)
#pragma unroll
                    for (int ma = 0; ma < 2; ma++)
#pragma unroll
                        for (int sub = 0; sub < 2; sub++)
                            mma16816(acc[ma][(nh2 * 2 + j) * 2 + sub], ahf[ma],
                                     blf[j][sub * 2], blf[j][sub * 2 + 1]);
#pragma unroll
                for (int j = 0; j < 2; j++)
#pragma unroll
                    for (int ma = 0; ma < 2; ma++)
#pragma unroll
                        for (int sub = 0; sub < 2; sub++)
                            mma16816(acc[ma][(nh2 * 2 + j) * 2 + sub], alf[ma],
                                     bhf[j][sub * 2], bhf[j][sub * 2 + 1]);
            }
        }
        if (++stg == 3) stg = 0;
    }
}

// ---------------------------------------------------------------------------
// QKV projection. Q/K: plain fp32 epilogue (rope happens in a separate
// kernel, as in R10 — keeps the GEMM tail short for 2-CTA overlap).
// V: in-register bf16 hi/lo split epilogue (no barrier, no fp32 buffer).
// ---------------------------------------------------------------------------
__global__ __launch_bounds__(256, 2)
void gemm_qkv_kernel() {
    extern __shared__ char smem[];
    int bx = blockIdx.x;
    int bm = blockIdx.y * 128;
    int tid = threadIdx.x;
    int lane = tid & 31, wid = tid >> 5;
    int wm = wid & 3, wn = wid >> 2;

    const __nv_bfloat16 *Bh, *Bl;
    int N, bn;
    if (bx < 16) {
        Bh = g_wqh; Bl = g_wql; N = NH * HD; bn = bx * 128;
    } else if (bx < 20) {
        Bh = g_wkh; Bl = g_wkl; N = NKV * HD; bn = (bx - 16) * 128;
    } else {
        Bh = g_wvh; Bl = g_wvl; N = NKV * HD; bn = (bx - 20) * 128;
    }

    float acc[2][8][4];
    gemm_mainloop(g_xh, g_xl, Bh, Bl, N, HID, bm, bn, smem, acc);

    if (bx >= 20) {
        // V epilogue: direct bf16 split.
#pragma unroll
        for (int ma = 0; ma < 2; ma++) {
            int row0 = bm + wm * 32 + ma * 16 + (lane >> 2);
#pragma unroll
            for (int na = 0; na < 8; na++) {
                int col = bn + wn * 64 + na * 8 + (lane & 3) * 2;
                __nv_bfloat16 h0, l0, h1, l1;
                split1(acc[ma][na][0], h0, l0);
                split1(acc[ma][na][1], h1, l1);
                *(uint32_t*)(g_Vh + (size_t)row0 * 512 + col) = packbf(h0, h1);
                *(uint32_t*)(g_Vl + (size_t)row0 * 512 + col) = packbf(l0, l1);
                split1(acc[ma][na][2], h0, l0);
                split1(acc[ma][na][3], h1, l1);
                *(uint32_t*)(g_Vh + (size_t)(row0 + 8) * 512 + col) = packbf(h0, h1);
                *(uint32_t*)(g_Vl + (size_t)(row0 + 8) * 512 + col) = packbf(l0, l1);
            }
        }
        return;
    }

    float* C = (bx < 16) ? g_Q : g_K;
#pragma unroll
    for (int ma = 0; ma < 2; ma++) {
        int row = bm + wm * 32 + ma * 16 + (lane >> 2);
#pragma unroll
        for (int na = 0; na < 8; na++) {
            int col = bn + wn * 64 + na * 8 + (lane & 3) * 2;
            *(float2*)(C + (size_t)row * N + col) =
                make_float2(acc[ma][na][0], acc[ma][na][1]);
            *(float2*)(C + (size_t)(row + 8) * N + col) =
                make_float2(acc[ma][na][2], acc[ma][na][3]);
        }
    }
}

// Output projection: plain fp32 epilogue.
__global__ __launch_bounds__(256, 2)
void gemm_out_kernel(float* __restrict__ C) {
    extern __shared__ char smem[];
    int tid = threadIdx.x;
    int lane = tid & 31, wid = tid >> 5;
    int wm = wid & 3, wn = wid >> 2;
    int bm = blockIdx.y * 128, bn = blockIdx.x * 128;

    float acc[2][8][4];
    gemm_mainloop(g_oh, g_ol, g_woh, g_wol, HID, NH * HD, bm, bn, smem, acc);

#pragma unroll
    for (int ma = 0; ma < 2; ma++) {
        int row = bm + wm * 32 + ma * 16 + (lane >> 2);
#pragma unroll
        for (int na = 0; na < 8; na++) {
            int col = bn + wn * 64 + na * 8 + (lane & 3) * 2;
            *(float2*)(C + (size_t)row * HID + col) =
                make_float2(acc[ma][na][0], acc[ma][na][1]);
            *(float2*)(C + (size_t)(row + 8) * HID + col) =
                make_float2(acc[ma][na][2], acc[ma][na][3]);
        }
    }
}

// ---------------------------------------------------------------------------
// RoPE table + apply (apply also emits bf16 hi/lo splits) — R10 version
// ---------------------------------------------------------------------------
__global__ void rope_table_kernel() {
    int i = blockIdx.x * blockDim.x + threadIdx.x;
    if (i >= S * 64) return;
    int j = i & 63;
    int s = i >> 6;
    double ifd = exp(-((double)(2 * j) / 128.0) * log(10000.0));
    float invf = (float)ifd;
    float ang = (float)s * invf;
    double cd, sd;
    sincos((double)ang, &sd, &cd);
    g_rc[i] = (float)cd;
    g_rs[i] = (float)sd;
}

__global__ void rope_apply_split_kernel(float* __restrict__ x,
                                        __nv_bfloat16* __restrict__ hi,
                                        __nv_bfloat16* __restrict__ lo,
                                        int heads, int total) {
    int i = blockIdx.x * blockDim.x + threadIdx.x;
    if (i >= total) return;
    int j = i & 63;
    int rest = i >> 6;
    int h = rest % heads;
    int bs = rest / heads;
    int s = bs & (S - 1);
    float c = g_rc[s * 64 + j];
    float sn = g_rs[s * 64 + j];
    size_t base = ((size_t)bs * heads + h) * HD;
    float x1 = x[base + j], x2 = x[base + j + 64];
    float y1 = x1 * c - x2 * sn;
    float y2 = x2 * c + x1 * sn;
    x[base + j] = y1;
    x[base + j + 64] = y2;
    __nv_bfloat16 h1, l1, h2, l2;
    split1(y1, h1, l1);
    split1(y2, h2, l2);
    hi[base + j] = h1;
    lo[base + j] = l1;
    hi[base + j + 64] = h2;
    lo[base + j + 64] = l2;
}

// ---------------------------------------------------------------------------
// Per-chunk K mean + selection
// ---------------------------------------------------------------------------
__global__ void kmean_kernel() {
    int id = blockIdx.x;
    int kvh = id & 3;
    int n = (id >> 2) & 7;
    int b = id >> 5;
    int d = threadIdx.x;
    const float* base = g_K + (((size_t)b * S + n * CHUNK) * NKV + kvh) * HD + d;
    float s = 0.f;
#pragma unroll 8
    for (int i = 0; i < CHUNK; i++) s += base[(size_t)i * NKV * HD];
    g_kmean[((b * NCH + n) * NKV + kvh) * HD + d] = s * (1.0f / CHUNK);
}

__global__ void select_kernel() {
    int w = blockIdx.x * (blockDim.x >> 5) + (threadIdx.x >> 5);
    int lane = threadIdx.x & 31;
    int s = w & (S - 1);
    int h = (w >> 11) & (NH - 1);
    int b = w >> 15;
    int kvh = h >> 2;
    int qc = s >> 8;

    const float* q = g_Q + (((size_t)b * S + s) * NH + h) * HD;
    float4 qv = *(const float4*)(q + lane * 4);
    float g[8];
    for (int n = 0; n < qc; n++) {
        const float* km = g_kmean + ((b * NCH + n) * NKV + kvh) * HD;
        float4 kv = *(const float4*)(km + lane * 4);
        float p = qv.x * kv.x + qv.y * kv.y + qv.z * kv.z + qv.w * kv.w;
#pragma unroll
        for (int o = 16; o; o >>= 1) p += __shfl_xor_sync(0xffffffffu, p, o);
        g[n] = p;
    }
    if (lane == 0) {
        unsigned sel = 1u << qc;
        for (int it = 0; it < 3; it++) {
            float best = 0.f;
            int bi = -1;
            for (int n = 0; n < qc; n++)
                if (!((sel >> n) & 1) && (bi < 0 || g[n] > best)) { best = g[n]; bi = n; }
            if (bi >= 0) sel |= 1u << bi;
        }
        g_sel[w] = sel;
    }
}

// ===========================================================================
// Tensor-core sparse flash attention (R10 version: 3-stage cp.async K/V
// pipeline + per-warp chunk skip; no rescale vote).
// ===========================================================================
#define AQ 128
#define AK 32
#define ASTR 136

#define KVSTAGE_B (4 * AK * ASTR * 2)
#define OFF_KH 0
#define OFF_KL (AK * ASTR * 2)
#define OFF_VH (2 * AK * ASTR * 2)
#define OFF_VL (3 * AK * ASTR * 2)
#define AT_Q_ELEMS (2 * AQ * ASTR)
#define AT_KV0_B (AT_Q_ELEMS * 2)
#define AT_BF16_B (AT_KV0_B + 3 * KVSTAGE_B)
#define AT_SMEM_BYTES (AT_BF16_B + AQ * 4 + 16 + 160)

__device__ __forceinline__ void attn_issue_kv(uint32_t st, int b, int kvh,
                                              int kt, int tid) {
    int row = tid >> 3;
    size_t gk = (((size_t)b * S + kt * AK + row) * NKV + kvh) * HD;
#pragma unroll
    for (int i = 0; i < 2; i++) {
        int g = (tid & 7) * 2 + i;
        uint32_t off = row * 272 + g * 16;
        cpa16(st + OFF_KH + off, g_Kh + gk + g * 8);
        cpa16(st + OFF_KL + off, g_Kl + gk + g * 8);
        cpa16(st + OFF_VH + off, g_Vh + gk + g * 8);
        cpa16(st + OFF_VL + off, g_Vl + gk + g * 8);
    }
    asm volatile("cp.async.commit_group;");
}

__global__ __launch_bounds__(256)
void attn_mma_kernel() {
    extern __shared__ __align__(16) char smc[];
    __nv_bfloat16* sQh = (__nv_bfloat16*)smc;
    __nv_bfloat16* sQl = sQh + AQ * ASTR;
    unsigned* selq = (unsigned*)(smc + AT_BF16_B);
    unsigned* selu_p = selq + AQ;
    int* cnt_p = (int*)(selu_p + 1);
    short* list = (short*)(cnt_p + 1);

    int qt = gridDim.x - 1 - blockIdx.x;
    int h = blockIdx.y, b = blockIdx.z;
    int kvh = h >> 2;
    int tid = threadIdx.x, lane = tid & 31, w = tid >> 5;
    int s0 = qt * AQ;
    int qc = s0 >> 8;

    {
        int r = tid >> 1, half = tid & 1;
        size_t gq = (((size_t)b * S + s0 + r) * NH + h) * HD + half * 64;
#pragma unroll
        for (int i = 0; i < 8; i++) {
            *(uint4*)&sQh[r * ASTR + half * 64 + i * 8] = *(const uint4*)(g_Qh + gq + i * 8);
            *(uint4*)&sQl[r * ASTR + half * 64 + i * 8] = *(const uint4*)(g_Ql + gq + i * 8);
        }
    }
    if (tid == 0) *selu_p = 0;
    __syncthreads();
    if (tid < AQ) {
        unsigned sv = g_sel[((size_t)(b * NH + h) << 11) + s0 + tid];
        selq[tid] = sv;
        atomicOr(selu_p, sv);
    }
    __syncthreads();
    if (tid == 0) {
        unsigned selu = *selu_p;
        int nkt = (s0 >> 5) + 4;
        int c = 0;
        for (int kt = 0; kt < nkt; kt++) {
            int n = kt >> 3;
            if (n < qc && !((selu >> n) & 1)) continue;
            list[c++] = (short)kt;
        }
        *cnt_p = c;
    }
    __syncthreads();
    int cnt = *cnt_p;

    unsigned selw = 0;
#pragma unroll
    for (int i = 0; i < 16; i++) selw |= selq[w * 16 + i];

    uint32_t kv0 = smem_u32(smc + AT_KV0_B);
    attn_issue_kv(kv0, b, kvh, list[0], tid);
    if (cnt > 1) attn_issue_kv(kv0 + KVSTAGE_B, b, kvh, list[1], tid);

    float acc[16][4];
#pragma unroll
    for (int j = 0; j < 16; j++)
#pragma unroll
        for (int k = 0; k < 4; k++) acc[j][k] = 0.f;
    float m0 = -1e30f, m1 = -1e30f, l0 = 0.f, l1 = 0.f;

    const float scale = 0.08838834764831845f;

    uint32_t qh_b = smem_u32(sQh), ql_b = smem_u32(sQl);
    uint32_t a_off = (uint32_t)(w * 16 + (lane & 15)) * 272 + (lane >> 4) * 16;
    uint32_t k_off = (uint32_t)((lane & 7) + (lane >> 4) * 8) * 272 + ((lane >> 3) & 1) * 16;
    uint32_t v_off = (uint32_t)(((lane >> 3) & 1) * 8 + (lane & 7)) * 272 + (lane >> 4) * 16;

    int r0 = w * 16 + (lane >> 2);
    int r1 = r0 + 8;

    int stg = 0;
    for (int i = 0; i < cnt; i++) {
        if (i + 1 < cnt)
            asm volatile("cp.async.wait_group 1;");
        else
            asm volatile("cp.async.wait_group 0;");
        __syncthreads();
        if (i + 2 < cnt) {
            int pst = stg + 2;
            if (pst >= 3) pst -= 3;
            attn_issue_kv(kv0 + pst * KVSTAGE_B, b, kvh, list[i + 2], tid);
        }

        int kt = list[i];
        int n = kt >> 3;
        bool past = (n < qc);
        uint32_t st = kv0 + stg * KVSTAGE_B;
        if (++stg == 3) stg = 0;

        if (past && !((selw >> n) & 1)) continue;

        uint32_t kh_b = st + OFF_KH, kl_b = st + OFF_KL;
        uint32_t vh_b = st + OFF_VH, vl_b = st + OFF_VL;

        float s[4][4];
#pragma unroll
        for (int nt = 0; nt < 4; nt++)
#pragma unroll
            for (int k = 0; k < 4; k++) s[nt][k] = 0.f;
#pragma unroll
        for (int ka = 0; ka < 8; ka++) {
            uint32_t aqh[4], aql[4], bh0[4], bh1[4], bl0[4], bl1[4];
            ldsm4(aqh, qh_b + a_off + ka * 32);
            ldsm4(aql, ql_b + a_off + ka * 32);
            ldsm4(bh0, kh_b + k_off + ka * 32);
            ldsm4(bh1, kh_b + k_off + 16 * 272 + ka * 32);
            ldsm4(bl0, kl_b + k_off + ka * 32);
            ldsm4(bl1, kl_b + k_off + 16 * 272 + ka * 32);
            mma16816(s[0], aqh, bh0[0], bh0[1]);
            mma16816(s[1], aqh, bh0[2], bh0[3]);
            mma16816(s[2], aqh, bh1[0], bh1[1]);
            mma16816(s[3], aqh, bh1[2], bh1[3]);
            mma16816(s[0], aqh, bl0[0], bl0[1]);
            mma16816(s[1], aqh, bl0[2], bl0[3]);
            mma16816(s[2], aqh, bl1[0], bl1[1]);
            mma16816(s[3], aqh, bl1[2], bl1[3]);
            mma16816(s[0], aql, bh0[0], bh0[1]);
            mma16816(s[1], aql, bh0[2], bh0[3]);
            mma16816(s[2], aql, bh1[0], bh1[1]);
            mma16816(s[3], aql, bh1[2], bh1[3]);
        }

        if (past) {
            bool ok0 = (selq[r0] >> n) & 1, ok1 = (selq[r1] >> n) & 1;
#pragma unroll
            for (int nt = 0; nt < 4; nt++) {
                s[nt][0] = ok0 ? s[nt][0] * scale : -3.0e38f;
                s[nt][1] = ok0 ? s[nt][1] * scale : -3.0e38f;
                s[nt][2] = ok1 ? s[nt][2] * scale : -3.0e38f;
                s[nt][3] = ok1 ? s[nt][3] * scale : -3.0e38f;
            }
        } else {
            int q0 = s0 + r0, q1 = s0 + r1;
#pragma unroll
            for (int nt = 0; nt < 4; nt++) {
                int t = kt * 32 + nt * 8 + (lane & 3) * 2;
                s[nt][0] = (t     <= q0) ? s[nt][0] * scale : -3.0e38f;
                s[nt][1] = (t + 1 <= q0) ? s[nt][1] * scale : -3.0e38f;
                s[nt][2] = (t     <= q1) ? s[nt][2] * scale : -3.0e38f;
                s[nt][3] = (t + 1 <= q1) ? s[nt][3] * scale : -3.0e38f;
            }
        }

        float mx0 = -3.0e38f, mx1 = -3.0e38f;
#pragma unroll
        for (int nt = 0; nt < 4; nt++) {
            mx0 = fmaxf(mx0, fmaxf(s[nt][0], s[nt][1]));
            mx1 = fmaxf(mx1, fmaxf(s[nt][2], s[nt][3]));
        }
        mx0 = fmaxf(mx0, __shfl_xor_sync(0xffffffffu, mx0, 1));
        mx0 = fmaxf(mx0, __shfl_xor_sync(0xffffffffu, mx0, 2));
        mx1 = fmaxf(mx1, __shfl_xor_sync(0xffffffffu, mx1, 1));
        mx1 = fmaxf(mx1, __shfl_xor_sync(0xffffffffu, mx1, 2));
        float mn0 = fmaxf(m0, mx0), mn1 = fmaxf(m1, mx1);
        float f0 = __expf(m0 - mn0), f1 = __expf(m1 - mn1);

        float sum0 = 0.f, sum1 = 0.f;
        uint32_t ph[4][2], pl[4][2];
#pragma unroll
        for (int nt = 0; nt < 4; nt++) {
            float p0 = __expf(s[nt][0] - mn0);
            float p1 = __expf(s[nt][1] - mn0);
            float p2 = __expf(s[nt][2] - mn1);
            float p3 = __expf(s[nt][3] - mn1);
            sum0 += p0 + p1;
            sum1 += p2 + p3;
            __nv_bfloat16 h0, h1, h2, h3, q0b, q1b, q2b, q3b;
            split1(p0, h0, q0b);
            split1(p1, h1, q1b);
            split1(p2, h2, q2b);
            split1(p3, h3, q3b);
            ph[nt][0] = packbf(h0, h1);
            ph[nt][1] = packbf(h2, h3);
            pl[nt][0] = packbf(q0b, q1b);
            pl[nt][1] = packbf(q2b, q3b);
        }
        sum0 += __shfl_xor_sync(0xffffffffu, sum0, 1);
        sum0 += __shfl_xor_sync(0xffffffffu, sum0, 2);
        sum1 += __shfl_xor_sync(0xffffffffu, sum1, 1);
        sum1 += __shfl_xor_sync(0xffffffffu, sum1, 2);
        l0 = l0 * f0 + sum0;
        l1 = l1 * f1 + sum1;
        m0 = mn0;
        m1 = mn1;
#pragma unroll
        for (int j = 0; j < 16; j++) {
            acc[j][0] *= f0;
            acc[j][1] *= f0;
            acc[j][2] *= f1;
            acc[j][3] *= f1;
        }

#pragma unroll
        for (int kg = 0; kg < 2; kg++) {
            uint32_t aPh[4] = {ph[kg * 2][0], ph[kg * 2][1], ph[kg * 2 + 1][0], ph[kg * 2 + 1][1]};
            uint32_t aPl[4] = {pl[kg * 2][0], pl[kg * 2][1], pl[kg * 2 + 1][0], pl[kg * 2 + 1][1]};
#pragma unroll
            for (int dn = 0; dn < 8; dn++) {
                uint32_t bvh[4], bvl[4];
                ldsm4t(bvh, vh_b + v_off + kg * 16 * 272 + dn * 32);
                ldsm4t(bvl, vl_b + v_off + kg * 16 * 272 + dn * 32);
                mma16816(acc[dn * 2],     aPh, bvh[0], bvh[1]);
                mma16816(acc[dn * 2 + 1], aPh, bvh[2], bvh[3]);
                mma16816(acc[dn * 2],     aPh, bvl[0], bvl[1]);
                mma16816(acc[dn * 2 + 1], aPh, bvl[2], bvl[3]);
                mma16816(acc[dn * 2],     aPl, bvh[0], bvh[1]);
                mma16816(acc[dn * 2 + 1], aPl, bvh[2], bvh[3]);
            }
        }
    }

    float inv0 = 1.0f / l0, inv1 = 1.0f / l1;
    size_t ob0 = (((size_t)b * S + s0 + r0) * NH + h) * HD;
    size_t ob1 = (((size_t)b * S + s0 + r1) * NH + h) * HD;
#pragma unroll
    for (int j = 0; j < 16; j++) {
        int d = j * 8 + (lane & 3) * 2;
        float o0 = acc[j][0] * inv0, o1 = acc[j][1] * inv0;
        float o2 = acc[j][2] * inv1, o3 = acc[j][3] * inv1;
        __nv_bfloat16 h0, h1, h2, h3, q0b, q1b, q2b, q3b;
        split1(o0, h0, q0b);
        split1(o1, h1, q1b);
        split1(o2, h2, q2b);
        split1(o3, h3, q3b);
        *(uint32_t*)(g_oh + ob0 + d) = packbf(h0, h1);
        *(uint32_t*)(g_ol + ob0 + d) = packbf(q0b, q1b);
        *(uint32_t*)(g_oh + ob1 + d) = packbf(h2, h3);
        *(uint32_t*)(g_ol + ob1 + d) = packbf(q2b, q3b);
    }
}

// ---------------------------------------------------------------------------
extern "C" void kernel_launch(void* const* d_in, const int* in_sizes, int n_in,
                              void* d_out, int out_size) {
    const float* x  = (const float*)d_in[0];
    const float* wq = (const float*)d_in[1];
    const float* wk = (const float*)d_in[2];
    const float* wv = (const float*)d_in[3];
    const float* wo = (const float*)d_in[4];
    float* out = (float*)d_out;

    float *Q, *K;
    cudaGetSymbolAddress((void**)&Q, g_Q);
    cudaGetSymbolAddress((void**)&K, g_K);

    __nv_bfloat16 *xh, *xl, *wqh, *wql, *wkh, *wkl, *wvh, *wvl, *woh, *wol;
    __nv_bfloat16 *Qh, *Ql, *Kh, *Kl;
    cudaGetSymbolAddress((void**)&xh, g_xh);
    cudaGetSymbolAddress((void**)&xl, g_xl);
    cudaGetSymbolAddress((void**)&wqh, g_wqh);
    cudaGetSymbolAddress((void**)&wql, g_wql);
    cudaGetSymbolAddress((void**)&wkh, g_wkh);
    cudaGetSymbolAddress((void**)&wkl, g_wkl);
    cudaGetSymbolAddress((void**)&wvh, g_wvh);
    cudaGetSymbolAddress((void**)&wvl, g_wvl);
    cudaGetSymbolAddress((void**)&woh, g_woh);
    cudaGetSymbolAddress((void**)&wol, g_wol);
    cudaGetSymbolAddress((void**)&Qh, g_Qh);
    cudaGetSymbolAddress((void**)&Ql, g_Ql);
    cudaGetSymbolAddress((void**)&Kh, g_Kh);
    cudaGetSymbolAddress((void**)&Kl, g_Kl);

    const int M = B * S;  // 4096
    cudaFuncSetAttribute(attn_mma_kernel,
                         cudaFuncAttributeMaxDynamicSharedMemorySize, AT_SMEM_BYTES);
    cudaFuncSetAttribute(gemm_qkv_kernel,
                         cudaFuncAttributeMaxDynamicSharedMemorySize, GEMM_SMEM);
    cudaFuncSetAttribute(gemm_out_kernel,
                         cudaFuncAttributeMaxDynamicSharedMemorySize, GEMM_SMEM);

    rope_table_kernel<<<(S * 64 + 255) / 256, 256>>>();

    // merged input/weight splits (one launch)
    {
        SplitArgs a;
        int n0 = (M * HID) / 4;            // x
        int n1 = (HID * NH * HD) / 4;      // wq
        int n2 = (HID * NKV * HD) / 4;     // wk
        int n3 = (HID * NKV * HD) / 4;     // wv
        int n4_ = (NH * HD * HID) / 4;     // wo
        a.in[0] = x;  a.hi[0] = xh;  a.lo[0] = xl;
        a.in[1] = wq; a.hi[1] = wqh; a.lo[1] = wql;
        a.in[2] = wk; a.hi[2] = wkh; a.lo[2] = wkl;
        a.in[3] = wv; a.hi[3] = wvh; a.lo[3] = wvl;
        a.in[4] = wo; a.hi[4] = woh; a.lo[4] = wol;
        a.start[0] = 0;
        a.start[1] = n0;
        a.start[2] = n0 + n1;
        a.start[3] = n0 + n1 + n2;
        a.start[4] = n0 + n1 + n2 + n3;
        a.total = n0 + n1 + n2 + n3 + n4_;
        split5_kernel<<<(a.total + 255) / 256, 256>>>(a);
    }

    // fused Q/K/V projections (V emits bf16 directly)
    gemm_qkv_kernel<<<dim3(24, 32), 256, GEMM_SMEM>>>();

    // RoPE + bf16 emission for Q/K
    {
        int totq = B * S * NH * 64;
        rope_apply_split_kernel<<<(totq + 255) / 256, 256>>>(Q, Qh, Ql, NH, totq);
        int totk = B * S * NKV * 64;
        rope_apply_split_kernel<<<(totk + 255) / 256, 256>>>(K, Kh, Kl, NKV, totk);
    }

    // chunk means + selection
    kmean_kernel<<<B * NCH * NKV, 128>>>();
    select_kernel<<<(B * NH * S) / 8, 256>>>();

    // tensor-core sparse attention
    attn_mma_kernel<<<dim3(S / AQ, NH, B), 256, AT_SMEM_BYTES>>>();

    // output projection
    gemm_out_kernel<<<dim3(16, 32), 256, GEMM_SMEM>>>(out);
}

// round 15
// speedup vs baseline: 1.0230x; 1.0164x over previous
#include <cuda_runtime.h>
#include <cuda_bf16.h>
#include <math.h>
#include <stdint.h>

// Problem constants
#define B 2
#define S 2048
#define HID 2048
#define NH 16
#define NKV 4
#define HD 128
#define CHUNK 256
#define NCH 8

// Scratch (static device allocations; no cudaMalloc allowed)
__device__ float g_Q[(size_t)B * S * NH * HD];
__device__ float g_K[(size_t)B * S * NKV * HD];
__device__ float g_V[(size_t)B * S * NKV * HD];
__device__ float g_kmean[(size_t)B * NCH * NKV * HD];
__device__ unsigned g_sel[(size_t)B * NH * S];
__device__ float g_rc[(size_t)S * 64];
__device__ float g_rs[(size_t)S * 64];

// bf16 hi/lo split copies
__device__ __nv_bfloat16 g_xh[(size_t)B * S * HID];
__device__ __nv_bfloat16 g_xl[(size_t)B * S * HID];
__device__ __nv_bfloat16 g_wqh[(size_t)HID * NH * HD];
__device__ __nv_bfloat16 g_wql[(size_t)HID * NH * HD];
__device__ __nv_bfloat16 g_wkh[(size_t)HID * NKV * HD];
__device__ __nv_bfloat16 g_wkl[(size_t)HID * NKV * HD];
__device__ __nv_bfloat16 g_wvh[(size_t)HID * NKV * HD];
__device__ __nv_bfloat16 g_wvl[(size_t)HID * NKV * HD];
__device__ __nv_bfloat16 g_woh[(size_t)NH * HD * HID];
__device__ __nv_bfloat16 g_wol[(size_t)NH * HD * HID];
__device__ __nv_bfloat16 g_oh[(size_t)B * S * NH * HD];
__device__ __nv_bfloat16 g_ol[(size_t)B * S * NH * HD];
// post-RoPE bf16 splits for attention
__device__ __nv_bfloat16 g_Qh[(size_t)B * S * NH * HD];
__device__ __nv_bfloat16 g_Ql[(size_t)B * S * NH * HD];
__device__ __nv_bfloat16 g_Kh[(size_t)B * S * NKV * HD];
__device__ __nv_bfloat16 g_Kl[(size_t)B * S * NKV * HD];
__device__ __nv_bfloat16 g_Vh[(size_t)B * S * NKV * HD];
__device__ __nv_bfloat16 g_Vl[(size_t)B * S * NKV * HD];

// ===========================================================================
// helpers
// ===========================================================================
__device__ __forceinline__ uint32_t smem_u32(const void* p) {
    uint32_t a;
    asm("{ .reg .u64 t; cvta.to.shared.u64 t, %1; cvt.u32.u64 %0, t; }"
        : "=r"(a) : "l"(p));
    return a;
}

__device__ __forceinline__ void ldsm4(uint32_t* r, uint32_t addr) {
    asm volatile("ldmatrix.sync.aligned.m8n8.x4.shared.b16 {%0,%1,%2,%3}, [%4];"
                 : "=r"(r[0]), "=r"(r[1]), "=r"(r[2]), "=r"(r[3]) : "r"(addr));
}
__device__ __forceinline__ void ldsm4t(uint32_t* r, uint32_t addr) {
    asm volatile("ldmatrix.sync.aligned.m8n8.x4.trans.shared.b16 {%0,%1,%2,%3}, [%4];"
                 : "=r"(r[0]), "=r"(r[1]), "=r"(r[2]), "=r"(r[3]) : "r"(addr));
}
__device__ __forceinline__ void mma16816(float* c, const uint32_t* a,
                                         uint32_t b0, uint32_t b1) {
    asm volatile(
        "mma.sync.aligned.m16n8k16.row.col.f32.bf16.bf16.f32 "
        "{%0,%1,%2,%3}, {%4,%5,%6,%7}, {%8,%9}, {%0,%1,%2,%3};"
        : "+f"(c[0]), "+f"(c[1]), "+f"(c[2]), "+f"(c[3])
        : "r"(a[0]), "r"(a[1]), "r"(a[2]), "r"(a[3]), "r"(b0), "r"(b1));
}
__device__ __forceinline__ void cpa16(uint32_t s, const void* g) {
    asm volatile("cp.async.cg.shared.global [%0], [%1], 16;" :: "r"(s), "l"(g));
}

// mbarrier helpers (all sm_80-baseline PTX; no arch-suffix features)
#define MBAR_INIT(addr, cnt) \
    asm volatile("mbarrier.init.shared.b64 [%0], %1;" \
                 :: "r"((uint32_t)(addr)), "r"((uint32_t)(cnt)) : "memory")
#define MBAR_ARRIVE(addr) \
    asm volatile("{\n\t.reg .b64 t;\n\tmbarrier.arrive.shared.b64 t, [%0];\n\t}" \
                 :: "r"((uint32_t)(addr)) : "memory")
#define CPASYNC_MBAR_ARRIVE(addr) \
    asm volatile("cp.async.mbarrier.arrive.noinc.shared.b64 [%0];" \
                 :: "r"((uint32_t)(addr)) : "memory")
#define MBAR_WAIT(addr, par) do {                                            \
    uint32_t _done = 0;                                                      \
    uint32_t _a = (uint32_t)(addr);                                          \
    uint32_t _p = (uint32_t)(par);                                           \
    while (!_done) {                                                         \
        asm volatile("{\n\t.reg .pred p;\n\t"                                \
            "mbarrier.test_wait.parity.shared.b64 p, [%1], %2;\n\t"          \
            "selp.b32 %0, 1, 0, p;\n\t}"                                     \
            : "=r"(_done) : "r"(_a), "r"(_p) : "memory");                    \
    }                                                                        \
} while (0)

__device__ __forceinline__ void split1(float a, __nv_bfloat16& h, __nv_bfloat16& l) {
    h = __float2bfloat16_rn(a);
    l = __float2bfloat16_rn(a - __bfloat162float(h));
}
__device__ __forceinline__ uint32_t packbf(__nv_bfloat16 lo, __nv_bfloat16 hi) {
    return ((uint32_t)__bfloat16_as_ushort(hi) << 16) | __bfloat16_as_ushort(lo);
}

// ---------------------------------------------------------------------------
// split kernel: fp32 -> bf16 hi + lo
// ---------------------------------------------------------------------------
__global__ void split_kernel(const float* __restrict__ in,
                             __nv_bfloat16* __restrict__ hi,
                             __nv_bfloat16* __restrict__ lo, int n4) {
    int i = blockIdx.x * blockDim.x + threadIdx.x;
    if (i >= n4) return;
    float4 v = ((const float4*)in)[i];
    __nv_bfloat16 h0, h1, h2, h3, l0, l1, l2, l3;
    split1(v.x, h0, l0);
    split1(v.y, h1, l1);
    split1(v.z, h2, l2);
    split1(v.w, h3, l3);
    ((uint2*)hi)[i] = make_uint2(packbf(h0, h1), packbf(h2, h3));
    ((uint2*)lo)[i] = make_uint2(packbf(l0, l1), packbf(l2, l3));
}

// ===========================================================================
// bf16x3 GEMM, cp.async 3-stage pipeline, single barrier per iteration.
// (unchanged from R10)
// ===========================================================================
#define GBK 32
#define PAH 0
#define PAL 10240
#define PBH 20480
#define PBL 29184
#define PSTAGE 37888
#define GEMM_SMEM (3 * PSTAGE)

__device__ __forceinline__ void gemm_issue(
    uint32_t st, const __nv_bfloat16* Ah, const __nv_bfloat16* Al,
    const __nv_bfloat16* Bh, const __nv_bfloat16* Bl,
    int bm, int bn, int k0, int N, int K, int tid) {
#pragma unroll
    for (int i = 0; i < 2; i++) {
        int c = tid + i * 256;
        int row = c >> 2, q = c & 3;
        size_t g = (size_t)(bm + row) * K + k0 + q * 8;
        cpa16(st + PAH + row * 80 + q * 16, Ah + g);
        cpa16(st + PAL + row * 80 + q * 16, Al + g);
    }
#pragma unroll
    for (int i = 0; i < 2; i++) {
        int c = tid + i * 256;
        int row = c >> 4, q = c & 15;
        size_t g = (size_t)(k0 + row) * N + bn + q * 8;
        cpa16(st + PBH + row * 272 + q * 16, Bh + g);
        cpa16(st + PBL + row * 272 + q * 16, Bl + g);
    }
    asm volatile("cp.async.commit_group;");
}

__device__ __forceinline__ void gemm_body(
    const __nv_bfloat16* __restrict__ Ah, const __nv_bfloat16* __restrict__ Al,
    const __nv_bfloat16* __restrict__ Bh, const __nv_bfloat16* __restrict__ Bl,
    float* __restrict__ C, int N, int K, int bm, int bn, char* smem) {
    int tid = threadIdx.x;
    int lane = tid & 31, wid = tid >> 5;
    int wm = wid & 3, wn = wid >> 2;

    float acc[2][8][4];
#pragma unroll
    for (int i = 0; i < 2; i++)
#pragma unroll
        for (int j = 0; j < 8; j++)
#pragma unroll
            for (int k = 0; k < 4; k++) acc[i][j][k] = 0.f;

    uint32_t sb = smem_u32(smem);
    int l15 = lane & 15, l16 = lane >> 4;
    uint32_t a_off = (uint32_t)(wm * 32 + l15) * 80 + l16 * 16;
    uint32_t b_off = (uint32_t)(((lane >> 3) & 1) * 8 + (lane & 7)) * 272
                   + wn * 128 + l16 * 16;

    int niter = K / GBK;
    gemm_issue(sb, Ah, Al, Bh, Bl, bm, bn, 0, N, K, tid);
    gemm_issue(sb + PSTAGE, Ah, Al, Bh, Bl, bm, bn, GBK, N, K, tid);

    int stg = 0;
    for (int it = 0; it < niter; it++) {
        if (it + 1 < niter)
            asm volatile("cp.async.wait_group 1;");
        else
            asm volatile("cp.async.wait_group 0;");
        __syncthreads();
        if (it + 2 < niter) {
            int pst = stg + 2;
            if (pst >= 3) pst -= 3;
            gemm_issue(sb + pst * PSTAGE, Ah, Al, Bh, Bl,
                       bm, bn, (it + 2) * GBK, N, K, tid);
        }

        uint32_t st = sb + stg * PSTAGE;
        uint32_t ash = st + PAH, asl = st + PAL;
        uint32_t bsh = st + PBH, bsl = st + PBL;
#pragma unroll
        for (int ka = 0; ka < 2; ka++) {
            uint32_t ahf[2][4], alf[2][4];
            ldsm4(ahf[0], ash + a_off + ka * 32);
            ldsm4(ahf[1], ash + a_off + ka * 32 + 16 * 80);
            ldsm4(alf[0], asl + a_off + ka * 32);
            ldsm4(alf[1], asl + a_off + ka * 32 + 16 * 80);
#pragma unroll
            for (int nh2 = 0; nh2 < 2; nh2++) {
                uint32_t bhf[2][4], blf[2][4];
                uint32_t bo = b_off + ka * 16 * 272 + nh2 * 64;
                ldsm4t(bhf[0], bsh + bo);
                ldsm4t(bhf[1], bsh + bo + 32);
                ldsm4t(blf[0], bsl + bo);
                ldsm4t(blf[1], bsl + bo + 32);
#pragma unroll
                for (int j = 0; j < 2; j++)
#pragma unroll
                    for (int ma = 0; ma < 2; ma++)
#pragma unroll
                        for (int sub = 0; sub < 2; sub++)
                            mma16816(acc[ma][(nh2 * 2 + j) * 2 + sub], ahf[ma],
                                     bhf[j][sub * 2], bhf[j][sub * 2 + 1]);
#pragma unroll
                for (int j = 0; j < 2; j++)
#pragma unroll
                    for (int ma = 0; ma < 2; ma++)
#pragma unroll
                        for (int sub = 0; sub < 2; sub++)
                            mma16816(acc[ma][(nh2 * 2 + j) * 2 + sub], ahf[ma],
                                     blf[j][sub * 2], blf[j][sub * 2 + 1]);
#pragma unroll
                for (int j = 0; j < 2; j++)
#pragma unroll
                    for (int ma = 0; ma < 2; ma++)
#pragma unroll
                        for (int sub = 0; sub < 2; sub++)
                            mma16816(acc[ma][(nh2 * 2 + j) * 2 + sub], alf[ma],
                                     bhf[j][sub * 2], bhf[j][sub * 2 + 1]);
            }
        }
        if (++stg == 3) stg = 0;
    }

#pragma unroll
    for (int ma = 0; ma < 2; ma++) {
        int row = bm + wm * 32 + ma * 16 + (lane >> 2);
#pragma unroll
        for (int na = 0; na < 8; na++) {
            int col = bn + wn * 64 + na * 8 + (lane & 3) * 2;
            *(float2*)(C + (size_t)row * N + col) =
                make_float2(acc[ma][na][0], acc[ma][na][1]);
            *(float2*)(C + (size_t)(row + 8) * N + col) =
                make_float2(acc[ma][na][2], acc[ma][na][3]);
        }
    }
}

__global__ __launch_bounds__(256, 2)
void gemm_qkv_kernel() {
    extern __shared__ char smem[];
    int bx = blockIdx.x;
    const __nv_bfloat16 *Bh, *Bl;
    float* C;
    int N, bn;
    if (bx < 16) {
        Bh = g_wqh; Bl = g_wql; C = g_Q; N = NH * HD; bn = bx * 128;
    } else if (bx < 20) {
        Bh = g_wkh; Bl = g_wkl; C = g_K; N = NKV * HD; bn = (bx - 16) * 128;
    } else {
        Bh = g_wvh; Bl = g_wvl; C = g_V; N = NKV * HD; bn = (bx - 20) * 128;
    }
    gemm_body(g_xh, g_xl, Bh, Bl, C, N, HID, blockIdx.y * 128, bn, smem);
}

__global__ __launch_bounds__(256, 2)
void gemm_out_kernel(float* __restrict__ C) {
    extern __shared__ char smem[];
    gemm_body(g_oh, g_ol, g_woh, g_wol, C, HID, NH * HD,
              blockIdx.y * 128, blockIdx.x * 128, smem);
}

// ---------------------------------------------------------------------------
// RoPE table + apply (apply also emits bf16 hi/lo splits)
// ---------------------------------------------------------------------------
__global__ void rope_table_kernel() {
    int i = blockIdx.x * blockDim.x + threadIdx.x;
    if (i >= S * 64) return;
    int j = i & 63;
    int s = i >> 6;
    double ifd = exp(-((double)(2 * j) / 128.0) * log(10000.0));
    float invf = (float)ifd;
    float ang = (float)s * invf;
    double cd, sd;
    sincos((double)ang, &sd, &cd);
    g_rc[i] = (float)cd;
    g_rs[i] = (float)sd;
}

__global__ void rope_apply_split_kernel(float* __restrict__ x,
                                        __nv_bfloat16* __restrict__ hi,
                                        __nv_bfloat16* __restrict__ lo,
                                        int heads, int total) {
    int i = blockIdx.x * blockDim.x + threadIdx.x;
    if (i >= total) return;
    int j = i & 63;
    int rest = i >> 6;
    int h = rest % heads;
    int bs = rest / heads;
    int s = bs & (S - 1);
    float c = g_rc[s * 64 + j];
    float sn = g_rs[s * 64 + j];
    size_t base = ((size_t)bs * heads + h) * HD;
    float x1 = x[base + j], x2 = x[base + j + 64];
    float y1 = x1 * c - x2 * sn;
    float y2 = x2 * c + x1 * sn;
    x[base + j] = y1;
    x[base + j + 64] = y2;
    __nv_bfloat16 h1, l1, h2, l2;
    split1(y1, h1, l1);
    split1(y2, h2, l2);
    hi[base + j] = h1;
    lo[base + j] = l1;
    hi[base + j + 64] = h2;
    lo[base + j + 64] = l2;
}

// ---------------------------------------------------------------------------
// Per-chunk K mean + selection
// ---------------------------------------------------------------------------
__global__ void kmean_kernel() {
    int id = blockIdx.x;
    int kvh = id & 3;
    int n = (id >> 2) & 7;
    int b = id >> 5;
    int d = threadIdx.x;
    const float* base = g_K + (((size_t)b * S + n * CHUNK) * NKV + kvh) * HD + d;
    float s = 0.f;
#pragma unroll 8
    for (int i = 0; i < CHUNK; i++) s += base[(size_t)i * NKV * HD];
    g_kmean[((b * NCH + n) * NKV + kvh) * HD + d] = s * (1.0f / CHUNK);
}

__global__ void select_kernel() {
    int w = blockIdx.x * (blockDim.x >> 5) + (threadIdx.x >> 5);
    int lane = threadIdx.x & 31;
    int s = w & (S - 1);
    int h = (w >> 11) & (NH - 1);
    int b = w >> 15;
    int kvh = h >> 2;
    int qc = s >> 8;

    const float* q = g_Q + (((size_t)b * S + s) * NH + h) * HD;
    float4 qv = *(const float4*)(q + lane * 4);
    float g[8];
    for (int n = 0; n < qc; n++) {
        const float* km = g_kmean + ((b * NCH + n) * NKV + kvh) * HD;
        float4 kv = *(const float4*)(km + lane * 4);
        float p = qv.x * kv.x + qv.y * kv.y + qv.z * kv.z + qv.w * kv.w;
#pragma unroll
        for (int o = 16; o; o >>= 1) p += __shfl_xor_sync(0xffffffffu, p, o);
        g[n] = p;
    }
    if (lane == 0) {
        unsigned sel = 1u << qc;
        for (int it = 0; it < 3; it++) {
            float best = 0.f;
            int bi = -1;
            for (int n = 0; n < qc; n++)
                if (!((sel >> n) & 1) && (bi < 0 || g[n] > best)) { best = g[n]; bi = n; }
            if (bi >= 0) sel |= 1u << bi;
        }
        g_sel[w] = sel;
    }
}

// ===========================================================================
// Tensor-core sparse flash attention with mbarrier async pipeline.
// No per-tile __syncthreads -> warps de-phase, softmax latency hides behind
// neighboring warps' MMAs. Tile order per warp identical to R10 -> numerics
// bit-identical (rel_err must remain 2.383093e-05).
// ===========================================================================
#define AQ 128
#define AK 32
#define ASTR 136

#define KVSTAGE_B (4 * AK * ASTR * 2)
#define OFF_KH 0
#define OFF_KL (AK * ASTR * 2)
#define OFF_VH (2 * AK * ASTR * 2)
#define OFF_VL (3 * AK * ASTR * 2)
#define AT_Q_ELEMS (2 * AQ * ASTR)
#define AT_KV0_B (AT_Q_ELEMS * 2)
#define AT_BF16_B (AT_KV0_B + 3 * KVSTAGE_B)
// sel area: selq 512B, selu 4, cnt 4, list 128B -> mbarriers at +656 (8-aligned)
#define AT_MB_OFF (AT_BF16_B + 656)
#define AT_SMEM_BYTES (AT_MB_OFF + 6 * 8 + 16)

__device__ __forceinline__ void attn_issue_kv(uint32_t st, int b, int kvh,
                                              int kt, int tid) {
    int row = tid >> 3;
    size_t gk = (((size_t)b * S + kt * AK + row) * NKV + kvh) * HD;
#pragma unroll
    for (int i = 0; i < 2; i++) {
        int g = (tid & 7) * 2 + i;
        uint32_t off = row * 272 + g * 16;
        cpa16(st + OFF_KH + off, g_Kh + gk + g * 8);
        cpa16(st + OFF_KL + off, g_Kl + gk + g * 8);
        cpa16(st + OFF_VH + off, g_Vh + gk + g * 8);
        cpa16(st + OFF_VL + off, g_Vl + gk + g * 8);
    }
}

__global__ __launch_bounds__(256)
void attn_mma_kernel() {
    extern __shared__ __align__(16) char smc[];
    __nv_bfloat16* sQh = (__nv_bfloat16*)smc;
    __nv_bfloat16* sQl = sQh + AQ * ASTR;
    unsigned* selq = (unsigned*)(smc + AT_BF16_B);
    unsigned* selu_p = selq + AQ;
    int* cnt_p = (int*)(selu_p + 1);
    short* list = (short*)(cnt_p + 1);
    uint32_t mb = smem_u32(smc + AT_MB_OFF);    // full[0..2] then empty[0..2]

    int qt = gridDim.x - 1 - blockIdx.x;
    int h = blockIdx.y, b = blockIdx.z;
    int kvh = h >> 2;
    int tid = threadIdx.x, lane = tid & 31, w = tid >> 5;
    int s0 = qt * AQ;
    int qc = s0 >> 8;

    // ---- stage Q ----
    {
        int r = tid >> 1, half = tid & 1;
        size_t gq = (((size_t)b * S + s0 + r) * NH + h) * HD + half * 64;
#pragma unroll
        for (int i = 0; i < 8; i++) {
            *(uint4*)&sQh[r * ASTR + half * 64 + i * 8] = *(const uint4*)(g_Qh + gq + i * 8);
            *(uint4*)&sQl[r * ASTR + half * 64 + i * 8] = *(const uint4*)(g_Ql + gq + i * 8);
        }
    }
    if (tid == 0) {
        *selu_p = 0;
#pragma unroll
        for (int s = 0; s < 6; s++) MBAR_INIT(mb + s * 8, 256);
    }
    __syncthreads();
    if (tid < AQ) {
        unsigned sv = g_sel[((size_t)(b * NH + h) << 11) + s0 + tid];
        selq[tid] = sv;
        atomicOr(selu_p, sv);
    }
    __syncthreads();
    if (tid == 0) {
        unsigned selu = *selu_p;
        int nkt = (s0 >> 5) + 4;
        int c = 0;
        for (int kt = 0; kt < nkt; kt++) {
            int n = kt >> 3;
            if (n < qc && !((selu >> n) & 1)) continue;
            list[c++] = (short)kt;
        }
        *cnt_p = c;
    }
    __syncthreads();
    int cnt = *cnt_p;

    unsigned selw = 0;
#pragma unroll
    for (int i = 0; i < 16; i++) selw |= selq[w * 16 + i];

    uint32_t kv0 = smem_u32(smc + AT_KV0_B);

    // initial issues: tiles 0 and 1
    attn_issue_kv(kv0, b, kvh, list[0], tid);
    CPASYNC_MBAR_ARRIVE(mb + 0 * 8);
    if (cnt > 1) {
        attn_issue_kv(kv0 + KVSTAGE_B, b, kvh, list[1], tid);
        CPASYNC_MBAR_ARRIVE(mb + 1 * 8);
    }

    float acc[16][4];
#pragma unroll
    for (int j = 0; j < 16; j++)
#pragma unroll
        for (int k = 0; k < 4; k++) acc[j][k] = 0.f;
    float m0 = -1e30f, m1 = -1e30f, l0 = 0.f, l1 = 0.f;

    const float scale = 0.08838834764831845f;

    uint32_t qh_b = smem_u32(sQh), ql_b = smem_u32(sQl);
    uint32_t a_off = (uint32_t)(w * 16 + (lane & 15)) * 272 + (lane >> 4) * 16;
    uint32_t k_off = (uint32_t)((lane & 7) + (lane >> 4) * 8) * 272 + ((lane >> 3) & 1) * 16;
    uint32_t v_off = (uint32_t)(((lane >> 3) & 1) * 8 + (lane & 7)) * 272 + (lane >> 4) * 16;

    int r0 = w * 16 + (lane >> 2);
    int r1 = r0 + 8;

    for (int i = 0; i < cnt; i++) {
        int s = i % 3;
        int rnd = i / 3;

        // prefetch tile i+2 into stage (i+2)%3 after that stage's previous
        // consumers (tile i-1) are all done
        if (i + 2 < cnt) {
            int s2 = (i + 2) % 3;
            int r2 = (i + 2) / 3;
            if (r2 > 0) MBAR_WAIT(mb + 24 + s2 * 8, (r2 - 1) & 1);
            attn_issue_kv(kv0 + s2 * KVSTAGE_B, b, kvh, list[i + 2], tid);
            CPASYNC_MBAR_ARRIVE(mb + s2 * 8);
        }

        int kt = list[i];
        int n = kt >> 3;
        bool past = (n < qc);

        if (past && !((selw >> n) & 1)) {
            // warp-level skip: still participate in stage accounting
            MBAR_ARRIVE(mb + 24 + s * 8);
            continue;
        }

        MBAR_WAIT(mb + s * 8, rnd & 1);   // data ready

        uint32_t st = kv0 + s * KVSTAGE_B;
        uint32_t kh_b = st + OFF_KH, kl_b = st + OFF_KL;
        uint32_t vh_b = st + OFF_VH, vl_b = st + OFF_VL;

        float sc[4][4];
#pragma unroll
        for (int nt = 0; nt < 4; nt++)
#pragma unroll
            for (int k = 0; k < 4; k++) sc[nt][k] = 0.f;
#pragma unroll
        for (int ka = 0; ka < 8; ka++) {
            uint32_t aqh[4], aql[4], bh0[4], bh1[4], bl0[4], bl1[4];
            ldsm4(aqh, qh_b + a_off + ka * 32);
            ldsm4(aql, ql_b + a_off + ka * 32);
            ldsm4(bh0, kh_b + k_off + ka * 32);
            ldsm4(bh1, kh_b + k_off + 16 * 272 + ka * 32);
            ldsm4(bl0, kl_b + k_off + ka * 32);
            ldsm4(bl1, kl_b + k_off + 16 * 272 + ka * 32);
            mma16816(sc[0], aqh, bh0[0], bh0[1]);
            mma16816(sc[1], aqh, bh0[2], bh0[3]);
            mma16816(sc[2], aqh, bh1[0], bh1[1]);
            mma16816(sc[3], aqh, bh1[2], bh1[3]);
            mma16816(sc[0], aqh, bl0[0], bl0[1]);
            mma16816(sc[1], aqh, bl0[2], bl0[3]);
            mma16816(sc[2], aqh, bl1[0], bl1[1]);
            mma16816(sc[3], aqh, bl1[2], bl1[3]);
            mma16816(sc[0], aql, bh0[0], bh0[1]);
            mma16816(sc[1], aql, bh0[2], bh0[3]);
            mma16816(sc[2], aql, bh1[0], bh1[1]);
            mma16816(sc[3], aql, bh1[2], bh1[3]);
        }

        if (past) {
            bool ok0 = (selq[r0] >> n) & 1, ok1 = (selq[r1] >> n) & 1;
#pragma unroll
            for (int nt = 0; nt < 4; nt++) {
                sc[nt][0] = ok0 ? sc[nt][0] * scale : -3.0e38f;
                sc[nt][1] = ok0 ? sc[nt][1] * scale : -3.0e38f;
                sc[nt][2] = ok1 ? sc[nt][2] * scale : -3.0e38f;
                sc[nt][3] = ok1 ? sc[nt][3] * scale : -3.0e38f;
            }
        } else {
            int q0 = s0 + r0, q1 = s0 + r1;
#pragma unroll
            for (int nt = 0; nt < 4; nt++) {
                int t = kt * 32 + nt * 8 + (lane & 3) * 2;
                sc[nt][0] = (t     <= q0) ? sc[nt][0] * scale : -3.0e38f;
                sc[nt][1] = (t + 1 <= q0) ? sc[nt][1] * scale : -3.0e38f;
                sc[nt][2] = (t     <= q1) ? sc[nt][2] * scale : -3.0e38f;
                sc[nt][3] = (t + 1 <= q1) ? sc[nt][3] * scale : -3.0e38f;
            }
        }

        float mx0 = -3.0e38f, mx1 = -3.0e38f;
#pragma unroll
        for (int nt = 0; nt < 4; nt++) {
            mx0 = fmaxf(mx0, fmaxf(sc[nt][0], sc[nt][1]));
            mx1 = fmaxf(mx1, fmaxf(sc[nt][2], sc[nt][3]));
        }
        mx0 = fmaxf(mx0, __shfl_xor_sync(0xffffffffu, mx0, 1));
        mx0 = fmaxf(mx0, __shfl_xor_sync(0xffffffffu, mx0, 2));
        mx1 = fmaxf(mx1, __shfl_xor_sync(0xffffffffu, mx1, 1));
        mx1 = fmaxf(mx1, __shfl_xor_sync(0xffffffffu, mx1, 2));
        float mn0 = fmaxf(m0, mx0), mn1 = fmaxf(m1, mx1);
        float f0 = __expf(m0 - mn0), f1 = __expf(m1 - mn1);

        float sum0 = 0.f, sum1 = 0.f;
        uint32_t ph[4][2], pl[4][2];
#pragma unroll
        for (int nt = 0; nt < 4; nt++) {
            float p0 = __expf(sc[nt][0] - mn0);
            float p1 = __expf(sc[nt][1] - mn0);
            float p2 = __expf(sc[nt][2] - mn1);
            float p3 = __expf(sc[nt][3] - mn1);
            sum0 += p0 + p1;
            sum1 += p2 + p3;
            __nv_bfloat16 h0, h1, h2, h3, q0b, q1b, q2b, q3b;
            split1(p0, h0, q0b);
            split1(p1, h1, q1b);
            split1(p2, h2, q2b);
            split1(p3, h3, q3b);
            ph[nt][0] = packbf(h0, h1);
            ph[nt][1] = packbf(h2, h3);
            pl[nt][0] = packbf(q0b, q1b);
            pl[nt][1] = packbf(q2b, q3b);
        }
        sum0 += __shfl_xor_sync(0xffffffffu, sum0, 1);
        sum0 += __shfl_xor_sync(0xffffffffu, sum0, 2);
        sum1 += __shfl_xor_sync(0xffffffffu, sum1, 1);
        sum1 += __shfl_xor_sync(0xffffffffu, sum1, 2);
        l0 = l0 * f0 + sum0;
        l1 = l1 * f1 + sum1;
        m0 = mn0;
        m1 = mn1;
#pragma unroll
        for (int j = 0; j < 16; j++) {
            acc[j][0] *= f0;
            acc[j][1] *= f0;
            acc[j][2] *= f1;
            acc[j][3] *= f1;
        }

#pragma unroll
        for (int kg = 0; kg < 2; kg++) {
            uint32_t aPh[4] = {ph[kg * 2][0], ph[kg * 2][1], ph[kg * 2 + 1][0], ph[kg * 2 + 1][1]};
            uint32_t aPl[4] = {pl[kg * 2][0], pl[kg * 2][1], pl[kg * 2 + 1][0], pl[kg * 2 + 1][1]};
#pragma unroll
            for (int dn = 0; dn < 8; dn++) {
                uint32_t bvh[4], bvl[4];
                ldsm4t(bvh, vh_b + v_off + kg * 16 * 272 + dn * 32);
                ldsm4t(bvl, vl_b + v_off + kg * 16 * 272 + dn * 32);
                mma16816(acc[dn * 2],     aPh, bvh[0], bvh[1]);
                mma16816(acc[dn * 2 + 1], aPh, bvh[2], bvh[3]);
                mma16816(acc[dn * 2],     aPh, bvl[0], bvl[1]);
                mma16816(acc[dn * 2 + 1], aPh, bvl[2], bvl[3]);
                mma16816(acc[dn * 2],     aPl, bvh[0], bvh[1]);
                mma16816(acc[dn * 2 + 1], aPl, bvh[2], bvh[3]);
            }
        }

        // done reading this stage
        MBAR_ARRIVE(mb + 24 + s * 8);
    }

    float inv0 = 1.0f / l0, inv1 = 1.0f / l1;
    size_t ob0 = (((size_t)b * S + s0 + r0) * NH + h) * HD;
    size_t ob1 = (((size_t)b * S + s0 + r1) * NH + h) * HD;
#pragma unroll
    for (int j = 0; j < 16; j++) {
        int d = j * 8 + (lane & 3) * 2;
        float o0 = acc[j][0] * inv0, o1 = acc[j][1] * inv0;
        float o2 = acc[j][2] * inv1, o3 = acc[j][3] * inv1;
        __nv_bfloat16 h0, h1, h2, h3, q0b, q1b, q2b, q3b;
        split1(o0, h0, q0b);
        split1(o1, h1, q1b);
        split1(o2, h2, q2b);
        split1(o3, h3, q3b);
        *(uint32_t*)(g_oh + ob0 + d) = packbf(h0, h1);
        *(uint32_t*)(g_ol + ob0 + d) = packbf(q0b, q1b);
        *(uint32_t*)(g_oh + ob1 + d) = packbf(h2, h3);
        *(uint32_t*)(g_ol + ob1 + d) = packbf(q2b, q3b);
    }
}

// ---------------------------------------------------------------------------
extern "C" void kernel_launch(void* const* d_in, const int* in_sizes, int n_in,
                              void* d_out, int out_size) {
    const float* x  = (const float*)d_in[0];
    const float* wq = (const float*)d_in[1];
    const float* wk = (const float*)d_in[2];
    const float* wv = (const float*)d_in[3];
    const float* wo = (const float*)d_in[4];
    float* out = (float*)d_out;

    float *Q, *K, *V;
    cudaGetSymbolAddress((void**)&Q, g_Q);
    cudaGetSymbolAddress((void**)&K, g_K);
    cudaGetSymbolAddress((void**)&V, g_V);

    __nv_bfloat16 *xh, *xl, *wqh, *wql, *wkh, *wkl, *wvh, *wvl, *woh, *wol;
    __nv_bfloat16 *Qh, *Ql, *Kh, *Kl, *Vh, *Vl;
    cudaGetSymbolAddress((void**)&xh, g_xh);
    cudaGetSymbolAddress((void**)&xl, g_xl);
    cudaGetSymbolAddress((void**)&wqh, g_wqh);
    cudaGetSymbolAddress((void**)&wql, g_wql);
    cudaGetSymbolAddress((void**)&wkh, g_wkh);
    cudaGetSymbolAddress((void**)&wkl, g_wkl);
    cudaGetSymbolAddress((void**)&wvh, g_wvh);
    cudaGetSymbolAddress((void**)&wvl, g_wvl);
    cudaGetSymbolAddress((void**)&woh, g_woh);
    cudaGetSymbolAddress((void**)&wol, g_wol);
    cudaGetSymbolAddress((void**)&Qh, g_Qh);
    cudaGetSymbolAddress((void**)&Ql, g_Ql);
    cudaGetSymbolAddress((void**)&Kh, g_Kh);
    cudaGetSymbolAddress((void**)&Kl, g_Kl);
    cudaGetSymbolAddress((void**)&Vh, g_Vh);
    cudaGetSymbolAddress((void**)&Vl, g_Vl);

    const int M = B * S;  // 4096
    cudaFuncSetAttribute(attn_mma_kernel,
                         cudaFuncAttributeMaxDynamicSharedMemorySize, AT_SMEM_BYTES);
    cudaFuncSetAttribute(gemm_qkv_kernel,
                         cudaFuncAttributeMaxDynamicSharedMemorySize, GEMM_SMEM);
    cudaFuncSetAttribute(gemm_out_kernel,
                         cudaFuncAttributeMaxDynamicSharedMemorySize, GEMM_SMEM);

    rope_table_kernel<<<(S * 64 + 255) / 256, 256>>>();

    // pre-split inputs/weights
    {
        int n4;
        n4 = (M * HID) / 4;
        split_kernel<<<(n4 + 255) / 256, 256>>>(x, xh, xl, n4);
        n4 = (HID * NH * HD) / 4;
        split_kernel<<<(n4 + 255) / 256, 256>>>(wq, wqh, wql, n4);
        n4 = (HID * NKV * HD) / 4;
        split_kernel<<<(n4 + 255) / 256, 256>>>(wk, wkh, wkl, n4);
        split_kernel<<<(n4 + 255) / 256, 256>>>(wv, wvh, wvl, n4);
        n4 = (NH * HD * HID) / 4;
        split_kernel<<<(n4 + 255) / 256, 256>>>(wo, woh, wol, n4);
    }

    // fused Q/K/V projections (3-stage pipelined)
    gemm_qkv_kernel<<<dim3(24, 32), 256, GEMM_SMEM>>>();

    // RoPE + direct bf16 hi/lo emission
    {
        int totq = B * S * NH * 64;
        rope_apply_split_kernel<<<(totq + 255) / 256, 256>>>(Q, Qh, Ql, NH, totq);
        int totk = B * S * NKV * 64;
        rope_apply_split_kernel<<<(totk + 255) / 256, 256>>>(K, Kh, Kl, NKV, totk);
    }

    // V split (no rope)
    {
        int n4 = (B * S * NKV * HD) / 4;
        split_kernel<<<(n4 + 255) / 256, 256>>>(V, Vh, Vl, n4);
    }

    // chunk means + selection
    kmean_kernel<<<B * NCH * NKV, 128>>>();
    select_kernel<<<(B * NH * S) / 8, 256>>>();

    // tensor-core sparse attention (mbarrier async pipeline)
    attn_mma_kernel<<<dim3(S / AQ, NH, B), 256, AT_SMEM_BYTES>>>();

    // output projection (3-stage pipelined)
    gemm_out_kernel<<<dim3(16, 32), 256, GEMM_SMEM>>>(out);
}